// round 1
// baseline (speedup 1.0000x reference)
#include <cuda_runtime.h>
#include <cstdint>

#define BB 8
#define SS 2048
#define DD 512
#define HH 512

// ---------------- scratch (device globals; no cudaMalloc allowed) ----------------
__device__ float g_Wx[(size_t)BB * SS * DD];          //  32 MB
__device__ float g_sc[(size_t)BB * SS * SS];          // 134 MB
__device__ float g_rinraw[(size_t)BB * SS * 2 * DD];  //  64 MB
__device__ float g_rin[(size_t)BB * SS * 2 * DD];     //  64 MB
__device__ float g_xwf[(size_t)BB * SS * 3 * HH];     //  96 MB
__device__ float g_xwb[(size_t)BB * SS * 3 * HH];     //  96 MB
__device__ float g_hcat[(size_t)BB * SS * 2 * HH];    //  64 MB
__device__ float g_h[2][2][BB * HH];                  // double-buffered hidden state
__device__ unsigned g_bar[2];                         // per-direction barrier counters

// =====================================================================
// Generic fp32 GEMM: C = A @ op(B) (+ epilogue)
//   A: [M,K] row-major, lda
//   BMODE 0: B is [N,K] row-major (so op(B)=B^T)   BMODE 1: B is [K,N] row-major
//   EPI 0: none   1: +bias[n]   2: C = A[m,n]*sigmoid(acc) (needs N==K, reads A)
//   EPI 3: +bias[n] + R[m,n]
// Tiles: BM=BN=128, BK=8, 256 threads, 8x8 per thread. All dims assumed
// divisible (M%128==0, N%128==0, K%8==0) — true for every call here.
// =====================================================================
template <int BMODE, int EPI>
__global__ void __launch_bounds__(256, 2)
gemm128(const float* __restrict__ A, const float* __restrict__ B,
        float* __restrict__ C, int M, int N, int K,
        int lda, int ldb, int ldc,
        long sA, long sB, long sC,
        const float* __restrict__ bias,
        const float* __restrict__ R, int ldr, long sR)
{
    A += (long)blockIdx.z * sA;
    B += (long)blockIdx.z * sB;
    C += (long)blockIdx.z * sC;
    if (EPI == 3) R += (long)blockIdx.z * sR;

    __shared__ float As[8][128];
    __shared__ float Bs[8][128];

    const int tid = threadIdx.x;
    const int bm = blockIdx.y * 128;
    const int bn = blockIdx.x * 128;

    // A tile loader: 128 rows x 8 cols, one float4 per thread
    const int arow = tid >> 1;
    const int acol = (tid & 1) << 2;
    const float* Aptr = A + (long)(bm + arow) * lda + acol;

    // B tile loader
    int brow, bcol;
    const float* Bptr;
    if (BMODE == 0) {
        brow = tid >> 1; bcol = (tid & 1) << 2;
        Bptr = B + (long)(bn + brow) * ldb + bcol;
    } else {
        brow = tid >> 5; bcol = (tid & 31) << 2;
        Bptr = B + (long)brow * ldb + bn + bcol;
    }

    float4 aR = *(const float4*)Aptr;
    float4 bR = *(const float4*)Bptr;

    const int tm = (tid >> 4) << 3;
    const int tn = (tid & 15) << 3;

    float acc[8][8];
#pragma unroll
    for (int i = 0; i < 8; ++i)
#pragma unroll
        for (int j = 0; j < 8; ++j) acc[i][j] = 0.f;

    const int nk = K >> 3;
    for (int kt = 0; kt < nk; ++kt) {
        // stage current tile into smem (A transposed)
        As[acol + 0][arow] = aR.x;
        As[acol + 1][arow] = aR.y;
        As[acol + 2][arow] = aR.z;
        As[acol + 3][arow] = aR.w;
        if (BMODE == 0) {
            Bs[bcol + 0][brow] = bR.x;
            Bs[bcol + 1][brow] = bR.y;
            Bs[bcol + 2][brow] = bR.z;
            Bs[bcol + 3][brow] = bR.w;
        } else {
            *(float4*)&Bs[brow][bcol] = bR;
        }
        __syncthreads();

        // prefetch next tile into registers (hides global latency over compute)
        if (kt + 1 < nk) {
            aR = *(const float4*)(Aptr + (long)(kt + 1) * 8);
            if (BMODE == 0) bR = *(const float4*)(Bptr + (long)(kt + 1) * 8);
            else            bR = *(const float4*)(Bptr + (long)(kt + 1) * 8 * ldb);
        }

#pragma unroll
        for (int k = 0; k < 8; ++k) {
            float a[8], b[8];
            *(float4*)(a)     = *(float4*)&As[k][tm];
            *(float4*)(a + 4) = *(float4*)&As[k][tm + 4];
            *(float4*)(b)     = *(float4*)&Bs[k][tn];
            *(float4*)(b + 4) = *(float4*)&Bs[k][tn + 4];
#pragma unroll
            for (int i = 0; i < 8; ++i)
#pragma unroll
                for (int j = 0; j < 8; ++j)
                    acc[i][j] = fmaf(a[i], b[j], acc[i][j]);
        }
        __syncthreads();
    }

    // epilogue
#pragma unroll
    for (int i = 0; i < 8; ++i) {
        const long m = bm + tm + i;
#pragma unroll
        for (int jj = 0; jj < 8; jj += 4) {
            const int n = bn + tn + jj;
            float4 v = make_float4(acc[i][jj], acc[i][jj + 1], acc[i][jj + 2], acc[i][jj + 3]);
            if (EPI == 1 || EPI == 3) {
                float4 bb = *(const float4*)&bias[n];
                v.x += bb.x; v.y += bb.y; v.z += bb.z; v.w += bb.w;
            }
            if (EPI == 3) {
                float4 rr = *(const float4*)&R[m * ldr + n];
                v.x += rr.x; v.y += rr.y; v.z += rr.z; v.w += rr.w;
            }
            if (EPI == 2) {
                float4 av = *(const float4*)&A[m * lda + n];
                v.x = av.x * (1.f / (1.f + __expf(-v.x)));
                v.y = av.y * (1.f / (1.f + __expf(-v.y)));
                v.z = av.z * (1.f / (1.f + __expf(-v.z)));
                v.w = av.w * (1.f / (1.f + __expf(-v.w)));
            }
            *(float4*)&C[m * ldc + n] = v;
        }
    }
}

// =====================================================================
// Row softmax over [B*S, S] with diagonal mask (col == row%S -> -inf)
// =====================================================================
__global__ void softmax_kernel(float* __restrict__ s)
{
    const long row = blockIdx.x;
    const int i = (int)(row & (SS - 1));
    float* p = s + row * SS;
    const int tid = threadIdx.x;

    float vals[8];
    float mx = -1e30f;
#pragma unroll
    for (int u = 0; u < 8; ++u) {
        const int j = tid + u * 256;
        float v = p[j];
        if (j == i) v = -INFINITY;
        vals[u] = v;
        mx = fmaxf(mx, v);
    }
    __shared__ float red[256];
    red[tid] = mx;
    __syncthreads();
#pragma unroll
    for (int st = 128; st; st >>= 1) {
        if (tid < st) red[tid] = fmaxf(red[tid], red[tid + st]);
        __syncthreads();
    }
    mx = red[0];
    __syncthreads();

    float sum = 0.f;
#pragma unroll
    for (int u = 0; u < 8; ++u) {
        vals[u] = __expf(vals[u] - mx);   // exp(-inf - mx) == 0
        sum += vals[u];
    }
    red[tid] = sum;
    __syncthreads();
#pragma unroll
    for (int st = 128; st; st >>= 1) {
        if (tid < st) red[tid] += red[tid + st];
        __syncthreads();
    }
    const float inv = 1.f / red[0];
#pragma unroll
    for (int u = 0; u < 8; ++u) p[tid + u * 256] = vals[u] * inv;
}

// copy x into first half of rin_raw rows (float4 granularity)
__global__ void copy_x_kernel(const float* __restrict__ x, float* __restrict__ rinraw)
{
    const long i = (long)blockIdx.x * 256 + threadIdx.x;  // over (B*S*D)/4 float4s
    const long row = i >> 7;       // D/4 = 128 float4 per x row
    const long col = i & 127;
    ((float4*)rinraw)[row * (2 * DD / 4) + col] = ((const float4*)x)[i];
}

__global__ void init_kernel()
{
    const int t = blockIdx.x * 256 + threadIdx.x;
    float* h = &g_h[0][0][0];
    if (t < 2 * 2 * BB * HH) h[t] = 0.f;
    if (t < 2) g_bar[t] = 0u;
}

// =====================================================================
// Persistent bidirectional GRU.
// Grid: 128 CTAs = 2 dirs x 64 slices; 256 threads; warp w owns hidden
// column j = slice*8 + w for ALL 8 batches. Whh rows (r,z,n) for that
// column live in registers for the whole kernel (48 regs/lane).
// Per step: load full h (8 batches x 512) via L2-only loads into SMEM,
// 3 batched dots per warp per batch, pointwise gates, write new h into
// the other buffer + the output, then per-direction spin barrier.
// 128 CTAs < 148 SMs -> guaranteed co-resident (deadlock-free).
// =====================================================================
#define CPB 64

__global__ void __launch_bounds__(256, 1)
gru_kernel(const float* __restrict__ xw_f, const float* __restrict__ xw_b,
           const float* __restrict__ Whh_f, const float* __restrict__ Whh_b,
           const float* __restrict__ bhh_f, const float* __restrict__ bhh_b,
           float* __restrict__ hcat)
{
    const int cta = blockIdx.x;
    const int dir = cta / CPB;            // 0 fwd, 1 bwd
    const int slice = cta % CPB;
    const float* xw  = dir ? xw_b  : xw_f;
    const float* Whh = dir ? Whh_b : Whh_f;
    const float* bhh = dir ? bhh_b : bhh_f;

    const int tid = threadIdx.x;
    const int w = tid >> 5;
    const int lane = tid & 31;
    const int j = slice * 8 + w;          // hidden column owned by this warp

    // pin Whh rows j, H+j, 2H+j in registers (coalesced loads)
    float wr[16], wz[16], wn[16];
#pragma unroll
    for (int u = 0; u < 16; ++u) {
        wr[u] = Whh[(long)(j)            * HH + lane + 32 * u];
        wz[u] = Whh[(long)(HH + j)       * HH + lane + 32 * u];
        wn[u] = Whh[(long)(2 * HH + j)   * HH + lane + 32 * u];
    }
    const float br = bhh[j], bz = bhh[HH + j], bnb = bhh[2 * HH + j];

    __shared__ float h_s[BB * HH];        // 16 KB

    for (int step = 0; step < SS; ++step) {
        const int p = step & 1;
        const int tt = dir ? (SS - 1 - step) : step;

        // load previous h (L2-only: L1 is not coherent across CTAs)
        {
            const float4* src = (const float4*)(&g_h[p][dir][0]);
            for (int i2 = tid; i2 < (BB * HH) / 4; i2 += 256)
                ((float4*)h_s)[i2] = __ldcg(src + i2);
        }
        __syncthreads();

        // prefetch input-gate contributions for all batches (uniform per warp)
        float xr[BB], xz[BB], xn[BB];
#pragma unroll
        for (int b = 0; b < BB; ++b) {
            const float* xwrow = xw + (long)(b * SS + tt) * (3 * HH);
            xr[b] = __ldg(xwrow + j);
            xz[b] = __ldg(xwrow + HH + j);
            xn[b] = __ldg(xwrow + 2 * HH + j);
        }

#pragma unroll
        for (int b = 0; b < BB; ++b) {
            const float* hb_ = h_s + b * HH;
            float ar = 0.f, az = 0.f, an = 0.f;
#pragma unroll
            for (int u = 0; u < 16; ++u) {
                const float hv = hb_[lane + 32 * u];
                ar = fmaf(wr[u], hv, ar);
                az = fmaf(wz[u], hv, az);
                an = fmaf(wn[u], hv, an);
            }
#pragma unroll
            for (int off = 16; off; off >>= 1) {
                ar += __shfl_xor_sync(0xffffffffu, ar, off);
                az += __shfl_xor_sync(0xffffffffu, az, off);
                an += __shfl_xor_sync(0xffffffffu, an, off);
            }
            if (lane == 0) {
                const float hprev = hb_[j];
                const float r = 1.f / (1.f + __expf(-(xr[b] + ar + br)));
                const float z = 1.f / (1.f + __expf(-(xz[b] + az + bz)));
                const float n = tanhf(xn[b] + r * (an + bnb));
                const float hn = (1.f - z) * n + z * hprev;
                g_h[p ^ 1][dir][b * HH + j] = hn;
                hcat[(long)(b * SS + tt) * (2 * HH) + dir * HH + j] = hn;
            }
        }

        // per-direction barrier (release: fence by all writers, then arrive)
        __threadfence();
        __syncthreads();
        if (tid == 0) {
            atomicAdd(&g_bar[dir], 1u);
            const unsigned target = (unsigned)(CPB * (step + 1));
            volatile unsigned* vb = &g_bar[dir];
            while (*vb < target) __nanosleep(64);
            __threadfence();
        }
        __syncthreads();
    }
}

// =====================================================================
extern "C" void kernel_launch(void* const* d_in, const int* in_sizes, int n_in,
                              void* d_out, int out_size)
{
    (void)in_sizes; (void)n_in; (void)out_size;
    const float* x     = (const float*)d_in[0];
    const float* W     = (const float*)d_in[1];
    const float* Wg    = (const float*)d_in[2];
    const float* Wih_f = (const float*)d_in[3];
    const float* Whh_f = (const float*)d_in[4];
    const float* bih_f = (const float*)d_in[5];
    const float* bhh_f = (const float*)d_in[6];
    const float* Wih_b = (const float*)d_in[7];
    const float* Whh_b = (const float*)d_in[8];
    const float* bih_b = (const float*)d_in[9];
    const float* bhh_b = (const float*)d_in[10];
    const float* Wp    = (const float*)d_in[11];
    const float* bp    = (const float*)d_in[12];
    float* out = (float*)d_out;

    float *Wx, *sc, *rinraw, *rin, *xwf, *xwb, *hcat;
    cudaGetSymbolAddress((void**)&Wx,     g_Wx);
    cudaGetSymbolAddress((void**)&sc,     g_sc);
    cudaGetSymbolAddress((void**)&rinraw, g_rinraw);
    cudaGetSymbolAddress((void**)&rin,    g_rin);
    cudaGetSymbolAddress((void**)&xwf,    g_xwf);
    cudaGetSymbolAddress((void**)&xwb,    g_xwb);
    cudaGetSymbolAddress((void**)&hcat,   g_hcat);

    const int M = BB * SS;                       // 16384

    init_kernel<<<64, 256>>>();

    // Wx = x @ W^T                [M,512] x [512,512]
    gemm128<0, 0><<<dim3(DD / 128, M / 128, 1), 256>>>(
        x, W, Wx, M, DD, DD, DD, DD, DD, 0, 0, 0, nullptr, nullptr, 0, 0);

    // s[b] = Wx[b] @ x[b]^T       8 x [2048,2048,512]
    gemm128<0, 0><<<dim3(SS / 128, SS / 128, BB), 256>>>(
        Wx, x, sc, SS, SS, DD, DD, DD, SS,
        (long)SS * DD, (long)SS * DD, (long)SS * SS, nullptr, nullptr, 0, 0);

    // masked softmax rows
    softmax_kernel<<<M, 256>>>(sc);

    // rin_raw[:, :512] = x
    copy_x_kernel<<<(M * DD / 4) / 256, 256>>>(x, rinraw);

    // rin_raw[:, 512:] = a[b] @ x[b]     8 x [2048,512,2048]
    gemm128<1, 0><<<dim3(DD / 128, SS / 128, BB), 256>>>(
        sc, x, rinraw + DD, SS, DD, SS, SS, DD, 2 * DD,
        (long)SS * SS, (long)SS * DD, (long)SS * 2 * DD, nullptr, nullptr, 0, 0);

    // rin = rin_raw * sigmoid(rin_raw @ Wg^T)
    gemm128<0, 2><<<dim3(2 * DD / 128, M / 128, 1), 256>>>(
        rinraw, Wg, rin, M, 2 * DD, 2 * DD, 2 * DD, 2 * DD, 2 * DD,
        0, 0, 0, nullptr, nullptr, 0, 0);

    // xw = rin @ Wih^T + bih  (both directions)
    gemm128<0, 1><<<dim3(3 * HH / 128, M / 128, 1), 256>>>(
        rin, Wih_f, xwf, M, 3 * HH, 2 * DD, 2 * DD, 2 * DD, 3 * HH,
        0, 0, 0, bih_f, nullptr, 0, 0);
    gemm128<0, 1><<<dim3(3 * HH / 128, M / 128, 1), 256>>>(
        rin, Wih_b, xwb, M, 3 * HH, 2 * DD, 2 * DD, 2 * DD, 3 * HH,
        0, 0, 0, bih_b, nullptr, 0, 0);

    // bidirectional GRU -> hcat [M, 1024]
    gru_kernel<<<128, 256>>>(xwf, xwb, Whh_f, Whh_b, bhh_f, bhh_b, hcat);

    // out = x + hcat @ Wp^T + bp
    gemm128<0, 3><<<dim3(DD / 128, M / 128, 1), 256>>>(
        hcat, Wp, out, M, DD, 2 * HH, 2 * HH, 2 * HH, DD,
        0, 0, 0, bp, x, DD, 0);
}

// round 2
// speedup vs baseline: 1.1631x; 1.1631x over previous
#include <cuda_runtime.h>
#include <cstdint>

#define BB 8
#define SS 2048
#define DD 512
#define HH 512

// ---------------- scratch (device globals; no cudaMalloc allowed) ----------------
__device__ float g_Wx[(size_t)BB * SS * DD];          //  32 MB
__device__ float g_sc[(size_t)BB * SS * SS];          // 134 MB
__device__ float g_rinraw[(size_t)BB * SS * 2 * DD];  //  64 MB
__device__ float g_rin[(size_t)BB * SS * 2 * DD];     //  64 MB
__device__ float g_xwf[(size_t)BB * SS * 3 * HH];     //  96 MB
__device__ float g_xwb[(size_t)BB * SS * 3 * HH];     //  96 MB
__device__ float g_hcat[(size_t)BB * SS * 2 * HH];    //  64 MB
__device__ float g_h[2][2][BB * HH];                  // double-buffered hidden state
__device__ unsigned g_bar[2];                         // per-direction barrier counters

// =====================================================================
// fp32 SIMT GEMM (kept for the accuracy-critical attention-score path)
// C = A @ B^T ; A [M,K] row-major, B [N,K] row-major.
// =====================================================================
__global__ void __launch_bounds__(256, 2)
gemm128(const float* __restrict__ A, const float* __restrict__ B,
        float* __restrict__ C, int M, int N, int K,
        int lda, int ldb, int ldc,
        long sA, long sB, long sC)
{
    A += (long)blockIdx.z * sA;
    B += (long)blockIdx.z * sB;
    C += (long)blockIdx.z * sC;

    __shared__ float As[8][128];
    __shared__ float Bs[8][128];

    const int tid = threadIdx.x;
    const int bm = blockIdx.y * 128;
    const int bn = blockIdx.x * 128;

    const int arow = tid >> 1;
    const int acol = (tid & 1) << 2;
    const float* Aptr = A + (long)(bm + arow) * lda + acol;
    const float* Bptr = B + (long)(bn + arow) * ldb + acol;

    float4 aR = *(const float4*)Aptr;
    float4 bR = *(const float4*)Bptr;

    const int tm = (tid >> 4) << 3;
    const int tn = (tid & 15) << 3;

    float acc[8][8];
#pragma unroll
    for (int i = 0; i < 8; ++i)
#pragma unroll
        for (int j = 0; j < 8; ++j) acc[i][j] = 0.f;

    const int nk = K >> 3;
    for (int kt = 0; kt < nk; ++kt) {
        As[acol + 0][arow] = aR.x;
        As[acol + 1][arow] = aR.y;
        As[acol + 2][arow] = aR.z;
        As[acol + 3][arow] = aR.w;
        Bs[acol + 0][arow] = bR.x;
        Bs[acol + 1][arow] = bR.y;
        Bs[acol + 2][arow] = bR.z;
        Bs[acol + 3][arow] = bR.w;
        __syncthreads();

        if (kt + 1 < nk) {
            aR = *(const float4*)(Aptr + (long)(kt + 1) * 8);
            bR = *(const float4*)(Bptr + (long)(kt + 1) * 8);
        }

#pragma unroll
        for (int k = 0; k < 8; ++k) {
            float a[8], b[8];
            *(float4*)(a)     = *(float4*)&As[k][tm];
            *(float4*)(a + 4) = *(float4*)&As[k][tm + 4];
            *(float4*)(b)     = *(float4*)&Bs[k][tn];
            *(float4*)(b + 4) = *(float4*)&Bs[k][tn + 4];
#pragma unroll
            for (int i = 0; i < 8; ++i)
#pragma unroll
                for (int j = 0; j < 8; ++j)
                    acc[i][j] = fmaf(a[i], b[j], acc[i][j]);
        }
        __syncthreads();
    }

#pragma unroll
    for (int i = 0; i < 8; ++i) {
        const long m = bm + tm + i;
#pragma unroll
        for (int jj = 0; jj < 8; jj += 4) {
            const int n = bn + tn + jj;
            float4 v = make_float4(acc[i][jj], acc[i][jj + 1], acc[i][jj + 2], acc[i][jj + 3]);
            *(float4*)&C[m * ldc + n] = v;
        }
    }
}

// =====================================================================
// tf32 tensor-core GEMM (mma.sync.m16n8k8).
//   C[M,N] = A[M,K] @ op(B)  (+ epilogue)
//   BMODE 0: B [N,K] row-major (op = B^T, K contiguous)
//   BMODE 1: B [K,N] row-major (N contiguous)
//   EPI 0: none  1: +bias  2: C = A[m,n]*sigmoid(acc) (N==K)  3: +bias+R
// CTA 128x128x32, 256 threads, warp tile 64x32, XOR-swizzled smem,
// double-buffered, register-staged loads. All dims %128==0, K%32==0.
// =====================================================================
__device__ __forceinline__ uint32_t f2tf(float f) {
    uint32_t u; asm("cvt.rna.tf32.f32 %0, %1;" : "=r"(u) : "f"(f)); return u;
}

__device__ __forceinline__ void mma_tf32(float* c, const uint32_t* a, uint32_t b0, uint32_t b1) {
    asm volatile(
        "mma.sync.aligned.m16n8k8.row.col.f32.tf32.tf32.f32 "
        "{%0,%1,%2,%3}, {%4,%5,%6,%7}, {%8,%9}, {%0,%1,%2,%3};\n"
        : "+f"(c[0]), "+f"(c[1]), "+f"(c[2]), "+f"(c[3])
        : "r"(a[0]), "r"(a[1]), "r"(a[2]), "r"(a[3]), "r"(b0), "r"(b1));
}

template <int BMODE, int EPI>
__global__ void __launch_bounds__(256)
mma_gemm(const float* __restrict__ A, const float* __restrict__ B,
         float* __restrict__ C, int M, int N, int K,
         int lda, int ldb, int ldc,
         long sA, long sB, long sC,
         const float* __restrict__ bias,
         const float* __restrict__ R, int ldr)
{
    A += (long)blockIdx.z * sA;
    B += (long)blockIdx.z * sB;
    C += (long)blockIdx.z * sC;

    extern __shared__ uint32_t smbuf[];
    uint32_t* As = smbuf;           // [2][128*32]
    uint32_t* Bs = smbuf + 8192;    // [2][128*32]

    const int tid  = threadIdx.x;
    const int lane = tid & 31;
    const int warp = tid >> 5;
    const int gid  = lane >> 2;     // 0..7
    const int tig  = lane & 3;      // 0..3
    const int wm   = (warp >> 2) * 64;
    const int wn   = (warp & 3) * 32;
    const int bm   = blockIdx.y * 128;
    const int bn   = blockIdx.x * 128;

    float acc[4][4][4];
#pragma unroll
    for (int mt = 0; mt < 4; ++mt)
#pragma unroll
        for (int nt = 0; nt < 4; ++nt)
#pragma unroll
            for (int q = 0; q < 4; ++q) acc[mt][nt][q] = 0.f;

    // B mode1 per-thread constant frag offsets (k-part added per kstep)
    int b1off0[4], b1off1[4];
    if (BMODE == 1) {
#pragma unroll
        for (int nt = 0; nt < 4; ++nt) {
            const int n = wn + nt * 8 + gid;
            b1off0[nt] = tig * 128       + ((((n >> 2) ^ (tig << 2)) << 2) + (n & 3));
            b1off1[nt] = (tig + 4) * 128 + ((((n >> 2) ^ ((tig + 4) << 2)) << 2) + (n & 3));
        }
    }

    float4 ra[4], rb[4];

    // ---- global -> regs for k-tile kt ----
#define LDG_TILE(kt)                                                          \
    {                                                                         \
        _Pragma("unroll")                                                     \
        for (int i = 0; i < 4; ++i) {                                         \
            const int idx = tid + 256 * i;                                    \
            const int row = idx >> 3, c4 = idx & 7;                           \
            ra[i] = *(const float4*)(A + (long)(bm + row) * lda + (kt) * 32 + c4 * 4); \
        }                                                                     \
        if (BMODE == 0) {                                                     \
            _Pragma("unroll")                                                 \
            for (int i = 0; i < 4; ++i) {                                     \
                const int idx = tid + 256 * i;                                \
                const int row = idx >> 3, c4 = idx & 7;                       \
                rb[i] = *(const float4*)(B + (long)(bn + row) * ldb + (kt) * 32 + c4 * 4); \
            }                                                                 \
        } else {                                                              \
            _Pragma("unroll")                                                 \
            for (int i = 0; i < 4; ++i) {                                     \
                const int idx = tid + 256 * i;                                \
                const int row = idx >> 5, c4 = idx & 31;                      \
                rb[i] = *(const float4*)(B + (long)((kt) * 32 + row) * ldb + bn + c4 * 4); \
            }                                                                 \
        }                                                                     \
    }

    // ---- regs -> smem buffer buf (tf32 convert + XOR swizzle) ----
#define STS_TILE(buf)                                                         \
    {                                                                         \
        uint32_t* pa = As + (buf) * 4096;                                     \
        _Pragma("unroll")                                                     \
        for (int i = 0; i < 4; ++i) {                                         \
            const int idx = tid + 256 * i;                                    \
            const int row = idx >> 3, c4 = idx & 7;                           \
            uint4 v = make_uint4(f2tf(ra[i].x), f2tf(ra[i].y), f2tf(ra[i].z), f2tf(ra[i].w)); \
            *(uint4*)&pa[row * 32 + ((c4 ^ (row & 7)) << 2)] = v;             \
        }                                                                     \
        uint32_t* pb = Bs + (buf) * 4096;                                     \
        if (BMODE == 0) {                                                     \
            _Pragma("unroll")                                                 \
            for (int i = 0; i < 4; ++i) {                                     \
                const int idx = tid + 256 * i;                                \
                const int row = idx >> 3, c4 = idx & 7;                       \
                uint4 v = make_uint4(f2tf(rb[i].x), f2tf(rb[i].y), f2tf(rb[i].z), f2tf(rb[i].w)); \
                *(uint4*)&pb[row * 32 + ((c4 ^ (row & 7)) << 2)] = v;         \
            }                                                                 \
        } else {                                                              \
            _Pragma("unroll")                                                 \
            for (int i = 0; i < 4; ++i) {                                     \
                const int idx = tid + 256 * i;                                \
                const int row = idx >> 5, c4 = idx & 31;                      \
                uint4 v = make_uint4(f2tf(rb[i].x), f2tf(rb[i].y), f2tf(rb[i].z), f2tf(rb[i].w)); \
                *(uint4*)&pb[row * 128 + ((c4 ^ ((row & 7) << 2)) << 2)] = v; \
            }                                                                 \
        }                                                                     \
    }

    LDG_TILE(0);
    STS_TILE(0);
    __syncthreads();

    const int nk = K >> 5;
    int cur = 0;
    for (int kt = 0; kt < nk; ++kt) {
        if (kt + 1 < nk) LDG_TILE(kt + 1);

        const uint32_t* pa = As + cur * 4096;
        const uint32_t* pb = Bs + cur * 4096;
#pragma unroll
        for (int ks = 0; ks < 4; ++ks) {
            const int s0 = tig + (((2 * ks)     ^ gid) << 2);
            const int s1 = tig + (((2 * ks + 1) ^ gid) << 2);

            uint32_t afr[4][4];
#pragma unroll
            for (int mt = 0; mt < 4; ++mt) {
                const int r0 = (wm + mt * 16 + gid) * 32;
                const int r1 = r0 + 8 * 32;
                afr[mt][0] = pa[r0 + s0];
                afr[mt][1] = pa[r1 + s0];
                afr[mt][2] = pa[r0 + s1];
                afr[mt][3] = pa[r1 + s1];
            }
            uint32_t bfr[4][2];
#pragma unroll
            for (int nt = 0; nt < 4; ++nt) {
                if (BMODE == 0) {
                    const int nrow = (wn + nt * 8 + gid) * 32;
                    bfr[nt][0] = pb[nrow + s0];
                    bfr[nt][1] = pb[nrow + s1];
                } else {
                    bfr[nt][0] = pb[b1off0[nt] + ks * 1024];
                    bfr[nt][1] = pb[b1off1[nt] + ks * 1024];
                }
            }
#pragma unroll
            for (int mt = 0; mt < 4; ++mt)
#pragma unroll
                for (int nt = 0; nt < 4; ++nt)
                    mma_tf32(acc[mt][nt], afr[mt], bfr[nt][0], bfr[nt][1]);
        }

        if (kt + 1 < nk) {
            STS_TILE(cur ^ 1);
            __syncthreads();
            cur ^= 1;
        }
    }

    // ---- epilogue ----
#pragma unroll
    for (int mt = 0; mt < 4; ++mt) {
#pragma unroll
        for (int half = 0; half < 2; ++half) {
            const long row = bm + wm + mt * 16 + gid + half * 8;
#pragma unroll
            for (int nt = 0; nt < 4; ++nt) {
                const int col = bn + wn + nt * 8 + 2 * tig;
                float v0 = acc[mt][nt][half * 2 + 0];
                float v1 = acc[mt][nt][half * 2 + 1];
                if (EPI == 1 || EPI == 3) {
                    v0 += bias[col];
                    v1 += bias[col + 1];
                }
                if (EPI == 3) {
                    const float2 rr = *(const float2*)&R[row * ldr + col];
                    v0 += rr.x; v1 += rr.y;
                }
                if (EPI == 2) {
                    const float2 av = *(const float2*)&A[row * lda + col];
                    v0 = av.x * (1.f / (1.f + __expf(-v0)));
                    v1 = av.y * (1.f / (1.f + __expf(-v1)));
                }
                float2 o; o.x = v0; o.y = v1;
                *(float2*)&C[row * ldc + col] = o;
            }
        }
    }
#undef LDG_TILE
#undef STS_TILE
}

// =====================================================================
// Row softmax over [B*S, S] with diagonal mask (col == row%S -> -inf)
// =====================================================================
__global__ void softmax_kernel(float* __restrict__ s)
{
    const long row = blockIdx.x;
    const int i = (int)(row & (SS - 1));
    float* p = s + row * SS;
    const int tid = threadIdx.x;

    float vals[8];
    float mx = -1e30f;
#pragma unroll
    for (int u = 0; u < 8; ++u) {
        const int j = tid + u * 256;
        float v = p[j];
        if (j == i) v = -INFINITY;
        vals[u] = v;
        mx = fmaxf(mx, v);
    }
    __shared__ float red[256];
    red[tid] = mx;
    __syncthreads();
#pragma unroll
    for (int st = 128; st; st >>= 1) {
        if (tid < st) red[tid] = fmaxf(red[tid], red[tid + st]);
        __syncthreads();
    }
    mx = red[0];
    __syncthreads();

    float sum = 0.f;
#pragma unroll
    for (int u = 0; u < 8; ++u) {
        vals[u] = __expf(vals[u] - mx);
        sum += vals[u];
    }
    red[tid] = sum;
    __syncthreads();
#pragma unroll
    for (int st = 128; st; st >>= 1) {
        if (tid < st) red[tid] += red[tid + st];
        __syncthreads();
    }
    const float inv = 1.f / red[0];
#pragma unroll
    for (int u = 0; u < 8; ++u) p[tid + u * 256] = vals[u] * inv;
}

__global__ void copy_x_kernel(const float* __restrict__ x, float* __restrict__ rinraw)
{
    const long i = (long)blockIdx.x * 256 + threadIdx.x;
    const long row = i >> 7;
    const long col = i & 127;
    ((float4*)rinraw)[row * (2 * DD / 4) + col] = ((const float4*)x)[i];
}

__global__ void init_kernel()
{
    const int t = blockIdx.x * 256 + threadIdx.x;
    float* h = &g_h[0][0][0];
    if (t < 2 * 2 * BB * HH) h[t] = 0.f;
    if (t < 2) g_bar[t] = 0u;
}

// =====================================================================
// Persistent bidirectional GRU (unchanged from R1 — isolating mma change)
// =====================================================================
#define CPB 64

__global__ void __launch_bounds__(256, 1)
gru_kernel(const float* __restrict__ xw_f, const float* __restrict__ xw_b,
           const float* __restrict__ Whh_f, const float* __restrict__ Whh_b,
           const float* __restrict__ bhh_f, const float* __restrict__ bhh_b,
           float* __restrict__ hcat)
{
    const int cta = blockIdx.x;
    const int dir = cta / CPB;
    const int slice = cta % CPB;
    const float* xw  = dir ? xw_b  : xw_f;
    const float* Whh = dir ? Whh_b : Whh_f;
    const float* bhh = dir ? bhh_b : bhh_f;

    const int tid = threadIdx.x;
    const int w = tid >> 5;
    const int lane = tid & 31;
    const int j = slice * 8 + w;

    float wr[16], wz[16], wn[16];
#pragma unroll
    for (int u = 0; u < 16; ++u) {
        wr[u] = Whh[(long)(j)          * HH + lane + 32 * u];
        wz[u] = Whh[(long)(HH + j)     * HH + lane + 32 * u];
        wn[u] = Whh[(long)(2 * HH + j) * HH + lane + 32 * u];
    }
    const float br = bhh[j], bz = bhh[HH + j], bnb = bhh[2 * HH + j];

    __shared__ float h_s[BB * HH];

    for (int step = 0; step < SS; ++step) {
        const int p = step & 1;
        const int tt = dir ? (SS - 1 - step) : step;

        {
            const float4* src = (const float4*)(&g_h[p][dir][0]);
            for (int i2 = tid; i2 < (BB * HH) / 4; i2 += 256)
                ((float4*)h_s)[i2] = __ldcg(src + i2);
        }
        __syncthreads();

        float xr[BB], xz[BB], xn[BB];
#pragma unroll
        for (int b = 0; b < BB; ++b) {
            const float* xwrow = xw + (long)(b * SS + tt) * (3 * HH);
            xr[b] = __ldg(xwrow + j);
            xz[b] = __ldg(xwrow + HH + j);
            xn[b] = __ldg(xwrow + 2 * HH + j);
        }

#pragma unroll
        for (int b = 0; b < BB; ++b) {
            const float* hb_ = h_s + b * HH;
            float ar = 0.f, az = 0.f, an = 0.f;
#pragma unroll
            for (int u = 0; u < 16; ++u) {
                const float hv = hb_[lane + 32 * u];
                ar = fmaf(wr[u], hv, ar);
                az = fmaf(wz[u], hv, az);
                an = fmaf(wn[u], hv, an);
            }
#pragma unroll
            for (int off = 16; off; off >>= 1) {
                ar += __shfl_xor_sync(0xffffffffu, ar, off);
                az += __shfl_xor_sync(0xffffffffu, az, off);
                an += __shfl_xor_sync(0xffffffffu, an, off);
            }
            if (lane == 0) {
                const float hprev = hb_[j];
                const float r = 1.f / (1.f + __expf(-(xr[b] + ar + br)));
                const float z = 1.f / (1.f + __expf(-(xz[b] + az + bz)));
                const float n = tanhf(xn[b] + r * (an + bnb));
                const float hn = (1.f - z) * n + z * hprev;
                g_h[p ^ 1][dir][b * HH + j] = hn;
                hcat[(long)(b * SS + tt) * (2 * HH) + dir * HH + j] = hn;
            }
        }

        __threadfence();
        __syncthreads();
        if (tid == 0) {
            atomicAdd(&g_bar[dir], 1u);
            const unsigned target = (unsigned)(CPB * (step + 1));
            volatile unsigned* vb = &g_bar[dir];
            while (*vb < target) __nanosleep(64);
            __threadfence();
        }
        __syncthreads();
    }
}

// =====================================================================
extern "C" void kernel_launch(void* const* d_in, const int* in_sizes, int n_in,
                              void* d_out, int out_size)
{
    (void)in_sizes; (void)n_in; (void)out_size;
    const float* x     = (const float*)d_in[0];
    const float* W     = (const float*)d_in[1];
    const float* Wg    = (const float*)d_in[2];
    const float* Wih_f = (const float*)d_in[3];
    const float* Whh_f = (const float*)d_in[4];
    const float* bih_f = (const float*)d_in[5];
    const float* bhh_f = (const float*)d_in[6];
    const float* Wih_b = (const float*)d_in[7];
    const float* Whh_b = (const float*)d_in[8];
    const float* bih_b = (const float*)d_in[9];
    const float* bhh_b = (const float*)d_in[10];
    const float* Wp    = (const float*)d_in[11];
    const float* bp    = (const float*)d_in[12];
    float* out = (float*)d_out;

    float *Wx, *sc, *rinraw, *rin, *xwf, *xwb, *hcat;
    cudaGetSymbolAddress((void**)&Wx,     g_Wx);
    cudaGetSymbolAddress((void**)&sc,     g_sc);
    cudaGetSymbolAddress((void**)&rinraw, g_rinraw);
    cudaGetSymbolAddress((void**)&rin,    g_rin);
    cudaGetSymbolAddress((void**)&xwf,    g_xwf);
    cudaGetSymbolAddress((void**)&xwb,    g_xwb);
    cudaGetSymbolAddress((void**)&hcat,   g_hcat);

    const int M = BB * SS;
    const int SMEM = 65536;

    cudaFuncSetAttribute(mma_gemm<1, 0>, cudaFuncAttributeMaxDynamicSharedMemorySize, SMEM);
    cudaFuncSetAttribute(mma_gemm<0, 1>, cudaFuncAttributeMaxDynamicSharedMemorySize, SMEM);
    cudaFuncSetAttribute(mma_gemm<0, 2>, cudaFuncAttributeMaxDynamicSharedMemorySize, SMEM);
    cudaFuncSetAttribute(mma_gemm<0, 3>, cudaFuncAttributeMaxDynamicSharedMemorySize, SMEM);

    init_kernel<<<64, 256>>>();

    // Wx = x @ W^T (fp32, feeds softmax logits)
    gemm128<<<dim3(DD / 128, M / 128, 1), 256>>>(
        x, W, Wx, M, DD, DD, DD, DD, DD, 0, 0, 0);

    // s[b] = Wx[b] @ x[b]^T (fp32, softmax logits)
    gemm128<<<dim3(SS / 128, SS / 128, BB), 256>>>(
        Wx, x, sc, SS, SS, DD, DD, DD, SS,
        (long)SS * DD, (long)SS * DD, (long)SS * SS);

    softmax_kernel<<<M, 256>>>(sc);

    copy_x_kernel<<<(M * DD / 4) / 256, 256>>>(x, rinraw);

    // rin_raw[:, 512:] = a[b] @ x[b]   (tf32 mma, BMODE1)
    mma_gemm<1, 0><<<dim3(DD / 128, SS / 128, BB), 256, SMEM>>>(
        sc, x, rinraw + DD, SS, DD, SS, SS, DD, 2 * DD,
        (long)SS * SS, (long)SS * DD, (long)SS * 2 * DD, nullptr, nullptr, 0);

    // rin = rin_raw * sigmoid(rin_raw @ Wg^T)
    mma_gemm<0, 2><<<dim3(2 * DD / 128, M / 128, 1), 256, SMEM>>>(
        rinraw, Wg, rin, M, 2 * DD, 2 * DD, 2 * DD, 2 * DD, 2 * DD,
        0, 0, 0, nullptr, nullptr, 0);

    // xw = rin @ Wih^T + bih (both directions)
    mma_gemm<0, 1><<<dim3(3 * HH / 128, M / 128, 1), 256, SMEM>>>(
        rin, Wih_f, xwf, M, 3 * HH, 2 * DD, 2 * DD, 2 * DD, 3 * HH,
        0, 0, 0, bih_f, nullptr, 0);
    mma_gemm<0, 1><<<dim3(3 * HH / 128, M / 128, 1), 256, SMEM>>>(
        rin, Wih_b, xwb, M, 3 * HH, 2 * DD, 2 * DD, 2 * DD, 3 * HH,
        0, 0, 0, bih_b, nullptr, 0);

    // bidirectional GRU -> hcat [M, 1024]
    gru_kernel<<<128, 256>>>(xwf, xwb, Whh_f, Whh_b, bhh_f, bhh_b, hcat);

    // out = x + hcat @ Wp^T + bp
    mma_gemm<0, 3><<<dim3(DD / 128, M / 128, 1), 256, SMEM>>>(
        hcat, Wp, out, M, DD, 2 * HH, 2 * HH, 2 * HH, DD,
        0, 0, 0, bp, x, DD);
}

// round 3
// speedup vs baseline: 1.4601x; 1.2554x over previous
#include <cuda_runtime.h>
#include <cstdint>

#define BB 8
#define SS 2048
#define DD 512
#define HH 512

// ---------------- scratch (device globals; no cudaMalloc allowed) ----------------
__device__ float g_Wx[(size_t)BB * SS * DD];          //  32 MB
__device__ float g_sc[(size_t)BB * SS * SS];          // 134 MB
__device__ float g_rinraw[(size_t)BB * SS * 2 * DD];  //  64 MB
__device__ float g_rin[(size_t)BB * SS * 2 * DD];     //  64 MB
__device__ float g_xwf[(size_t)BB * SS * 3 * HH];     //  96 MB
__device__ float g_xwb[(size_t)BB * SS * 3 * HH];     //  96 MB
__device__ float g_hcat[(size_t)BB * SS * 2 * HH];    //  64 MB
__device__ float g_h[2][2][BB * HH];                  // double-buffered hidden state
__device__ unsigned g_bar[2];                         // per-direction barrier counters

// =====================================================================
// fp32 SIMT GEMM (accuracy-critical attention-score path)
// C = A @ B^T ; A [M,K] row-major, B [N,K] row-major.
// =====================================================================
__global__ void __launch_bounds__(256, 2)
gemm128(const float* __restrict__ A, const float* __restrict__ B,
        float* __restrict__ C, int M, int N, int K,
        int lda, int ldb, int ldc,
        long sA, long sB, long sC)
{
    A += (long)blockIdx.z * sA;
    B += (long)blockIdx.z * sB;
    C += (long)blockIdx.z * sC;

    __shared__ float As[8][128];
    __shared__ float Bs[8][128];

    const int tid = threadIdx.x;
    const int bm = blockIdx.y * 128;
    const int bn = blockIdx.x * 128;

    const int arow = tid >> 1;
    const int acol = (tid & 1) << 2;
    const float* Aptr = A + (long)(bm + arow) * lda + acol;
    const float* Bptr = B + (long)(bn + arow) * ldb + acol;

    float4 aR = *(const float4*)Aptr;
    float4 bR = *(const float4*)Bptr;

    const int tm = (tid >> 4) << 3;
    const int tn = (tid & 15) << 3;

    float acc[8][8];
#pragma unroll
    for (int i = 0; i < 8; ++i)
#pragma unroll
        for (int j = 0; j < 8; ++j) acc[i][j] = 0.f;

    const int nk = K >> 3;
    for (int kt = 0; kt < nk; ++kt) {
        As[acol + 0][arow] = aR.x;
        As[acol + 1][arow] = aR.y;
        As[acol + 2][arow] = aR.z;
        As[acol + 3][arow] = aR.w;
        Bs[acol + 0][arow] = bR.x;
        Bs[acol + 1][arow] = bR.y;
        Bs[acol + 2][arow] = bR.z;
        Bs[acol + 3][arow] = bR.w;
        __syncthreads();

        if (kt + 1 < nk) {
            aR = *(const float4*)(Aptr + (long)(kt + 1) * 8);
            bR = *(const float4*)(Bptr + (long)(kt + 1) * 8);
        }

#pragma unroll
        for (int k = 0; k < 8; ++k) {
            float a[8], b[8];
            *(float4*)(a)     = *(float4*)&As[k][tm];
            *(float4*)(a + 4) = *(float4*)&As[k][tm + 4];
            *(float4*)(b)     = *(float4*)&Bs[k][tn];
            *(float4*)(b + 4) = *(float4*)&Bs[k][tn + 4];
#pragma unroll
            for (int i = 0; i < 8; ++i)
#pragma unroll
                for (int j = 0; j < 8; ++j)
                    acc[i][j] = fmaf(a[i], b[j], acc[i][j]);
        }
        __syncthreads();
    }

#pragma unroll
    for (int i = 0; i < 8; ++i) {
        const long m = bm + tm + i;
#pragma unroll
        for (int jj = 0; jj < 8; jj += 4) {
            const int n = bn + tn + jj;
            float4 v = make_float4(acc[i][jj], acc[i][jj + 1], acc[i][jj + 2], acc[i][jj + 3]);
            *(float4*)&C[m * ldc + n] = v;
        }
    }
}

// =====================================================================
// tf32 tensor-core GEMM (mma.sync.m16n8k8), 512 threads, CTA 128x256x32,
// 16 warps (2m x 8n), warp tile 64x32, XOR-swizzled smem, double-buffered.
//   BMODE 0: B [N,K] row-major   BMODE 1: B [K,N] row-major
//   EPI 0 none / 1 +bias / 2 C=A*sigmoid(acc) (N==K) / 3 +bias+R
// =====================================================================
__device__ __forceinline__ uint32_t f2tf(float f) {
    uint32_t u; asm("cvt.rna.tf32.f32 %0, %1;" : "=r"(u) : "f"(f)); return u;
}

__device__ __forceinline__ void mma_tf32(float* c, const uint32_t* a, uint32_t b0, uint32_t b1) {
    asm volatile(
        "mma.sync.aligned.m16n8k8.row.col.f32.tf32.tf32.f32 "
        "{%0,%1,%2,%3}, {%4,%5,%6,%7}, {%8,%9}, {%0,%1,%2,%3};\n"
        : "+f"(c[0]), "+f"(c[1]), "+f"(c[2]), "+f"(c[3])
        : "r"(a[0]), "r"(a[1]), "r"(a[2]), "r"(a[3]), "r"(b0), "r"(b1));
}

template <int BMODE, int EPI>
__global__ void __launch_bounds__(512, 1)
mma_gemm(const float* __restrict__ A, const float* __restrict__ B,
         float* __restrict__ C, int M, int N, int K,
         int lda, int ldb, int ldc,
         long sA, long sB, long sC,
         const float* __restrict__ bias,
         const float* __restrict__ R, int ldr)
{
    A += (long)blockIdx.z * sA;
    B += (long)blockIdx.z * sB;
    C += (long)blockIdx.z * sC;

    extern __shared__ uint32_t smbuf[];
    uint32_t* As = smbuf;            // 2 x 4096 u32 (128x32)
    uint32_t* Bs = smbuf + 8192;     // 2 x 8192 u32 (256x32 / 32x256)

    const int tid  = threadIdx.x;
    const int lane = tid & 31;
    const int warp = tid >> 5;
    const int gid  = lane >> 2;
    const int tig  = lane & 3;
    const int wm   = (warp >> 3) * 64;
    const int wn   = (warp & 7) * 32;
    const int bm   = blockIdx.y * 128;
    const int bn   = blockIdx.x * 256;

    float acc[4][4][4];
#pragma unroll
    for (int mt = 0; mt < 4; ++mt)
#pragma unroll
        for (int nt = 0; nt < 4; ++nt)
#pragma unroll
            for (int q = 0; q < 4; ++q) acc[mt][nt][q] = 0.f;

    int b1off0[4], b1off1[4];
    if (BMODE == 1) {
#pragma unroll
        for (int nt = 0; nt < 4; ++nt) {
            const int n = wn + nt * 8 + gid;
            b1off0[nt] = tig * 256       + ((((n >> 2) ^ (tig << 2)) << 2) + (n & 3));
            b1off1[nt] = (tig + 4) * 256 + ((((n >> 2) ^ ((tig + 4) << 2)) << 2) + (n & 3));
        }
    }

    float4 ra[2], rb[4];

#define LDG_TILE(kt)                                                          \
    {                                                                         \
        _Pragma("unroll")                                                     \
        for (int i = 0; i < 2; ++i) {                                         \
            const int idx = tid + 512 * i;                                    \
            const int row = idx >> 3, c4 = idx & 7;                           \
            ra[i] = *(const float4*)(A + (long)(bm + row) * lda + (kt) * 32 + c4 * 4); \
        }                                                                     \
        if (BMODE == 0) {                                                     \
            _Pragma("unroll")                                                 \
            for (int i = 0; i < 4; ++i) {                                     \
                const int idx = tid + 512 * i;                                \
                const int row = idx >> 3, c4 = idx & 7;                       \
                rb[i] = *(const float4*)(B + (long)(bn + row) * ldb + (kt) * 32 + c4 * 4); \
            }                                                                 \
        } else {                                                              \
            _Pragma("unroll")                                                 \
            for (int i = 0; i < 4; ++i) {                                     \
                const int idx = tid + 512 * i;                                \
                const int row = idx >> 6, c4 = idx & 63;                      \
                rb[i] = *(const float4*)(B + (long)((kt) * 32 + row) * ldb + bn + c4 * 4); \
            }                                                                 \
        }                                                                     \
    }

#define STS_TILE(buf)                                                         \
    {                                                                         \
        uint32_t* pa = As + (buf) * 4096;                                     \
        _Pragma("unroll")                                                     \
        for (int i = 0; i < 2; ++i) {                                         \
            const int idx = tid + 512 * i;                                    \
            const int row = idx >> 3, c4 = idx & 7;                           \
            uint4 v = make_uint4(f2tf(ra[i].x), f2tf(ra[i].y), f2tf(ra[i].z), f2tf(ra[i].w)); \
            *(uint4*)&pa[row * 32 + ((c4 ^ (row & 7)) << 2)] = v;             \
        }                                                                     \
        uint32_t* pb = Bs + (buf) * 8192;                                     \
        if (BMODE == 0) {                                                     \
            _Pragma("unroll")                                                 \
            for (int i = 0; i < 4; ++i) {                                     \
                const int idx = tid + 512 * i;                                \
                const int row = idx >> 3, c4 = idx & 7;                       \
                uint4 v = make_uint4(f2tf(rb[i].x), f2tf(rb[i].y), f2tf(rb[i].z), f2tf(rb[i].w)); \
                *(uint4*)&pb[row * 32 + ((c4 ^ (row & 7)) << 2)] = v;         \
            }                                                                 \
        } else {                                                              \
            _Pragma("unroll")                                                 \
            for (int i = 0; i < 4; ++i) {                                     \
                const int idx = tid + 512 * i;                                \
                const int row = idx >> 6, c4 = idx & 63;                      \
                uint4 v = make_uint4(f2tf(rb[i].x), f2tf(rb[i].y), f2tf(rb[i].z), f2tf(rb[i].w)); \
                *(uint4*)&pb[row * 256 + ((c4 ^ ((row & 7) << 2)) << 2)] = v; \
            }                                                                 \
        }                                                                     \
    }

    LDG_TILE(0);
    STS_TILE(0);
    __syncthreads();

    const int nk = K >> 5;
    int cur = 0;
    for (int kt = 0; kt < nk; ++kt) {
        if (kt + 1 < nk) LDG_TILE(kt + 1);

        const uint32_t* pa = As + cur * 4096;
        const uint32_t* pb = Bs + cur * 8192;
#pragma unroll
        for (int ks = 0; ks < 4; ++ks) {
            const int s0 = tig + (((2 * ks)     ^ gid) << 2);
            const int s1 = tig + (((2 * ks + 1) ^ gid) << 2);

            uint32_t afr[4][4];
#pragma unroll
            for (int mt = 0; mt < 4; ++mt) {
                const int r0 = (wm + mt * 16 + gid) * 32;
                const int r1 = r0 + 8 * 32;
                afr[mt][0] = pa[r0 + s0];
                afr[mt][1] = pa[r1 + s0];
                afr[mt][2] = pa[r0 + s1];
                afr[mt][3] = pa[r1 + s1];
            }
            uint32_t bfr[4][2];
#pragma unroll
            for (int nt = 0; nt < 4; ++nt) {
                if (BMODE == 0) {
                    const int nrow = (wn + nt * 8 + gid) * 32;
                    bfr[nt][0] = pb[nrow + s0];
                    bfr[nt][1] = pb[nrow + s1];
                } else {
                    bfr[nt][0] = pb[b1off0[nt] + ks * 2048];
                    bfr[nt][1] = pb[b1off1[nt] + ks * 2048];
                }
            }
#pragma unroll
            for (int mt = 0; mt < 4; ++mt)
#pragma unroll
                for (int nt = 0; nt < 4; ++nt)
                    mma_tf32(acc[mt][nt], afr[mt], bfr[nt][0], bfr[nt][1]);
        }

        if (kt + 1 < nk) {
            STS_TILE(cur ^ 1);
            __syncthreads();
            cur ^= 1;
        }
    }

#pragma unroll
    for (int mt = 0; mt < 4; ++mt) {
#pragma unroll
        for (int half = 0; half < 2; ++half) {
            const long row = bm + wm + mt * 16 + gid + half * 8;
#pragma unroll
            for (int nt = 0; nt < 4; ++nt) {
                const int col = bn + wn + nt * 8 + 2 * tig;
                float v0 = acc[mt][nt][half * 2 + 0];
                float v1 = acc[mt][nt][half * 2 + 1];
                if (EPI == 1 || EPI == 3) {
                    v0 += bias[col];
                    v1 += bias[col + 1];
                }
                if (EPI == 3) {
                    const float2 rr = *(const float2*)&R[row * ldr + col];
                    v0 += rr.x; v1 += rr.y;
                }
                if (EPI == 2) {
                    const float2 av = *(const float2*)&A[row * lda + col];
                    v0 = av.x * (1.f / (1.f + __expf(-v0)));
                    v1 = av.y * (1.f / (1.f + __expf(-v1)));
                }
                float2 o; o.x = v0; o.y = v1;
                *(float2*)&C[row * ldc + col] = o;
            }
        }
    }
#undef LDG_TILE
#undef STS_TILE
}

// =====================================================================
// Row softmax over [B*S, S] with diagonal mask
// =====================================================================
__global__ void softmax_kernel(float* __restrict__ s)
{
    const long row = blockIdx.x;
    const int i = (int)(row & (SS - 1));
    float* p = s + row * SS;
    const int tid = threadIdx.x;

    float vals[8];
    float mx = -1e30f;
#pragma unroll
    for (int u = 0; u < 8; ++u) {
        const int j = tid + u * 256;
        float v = p[j];
        if (j == i) v = -INFINITY;
        vals[u] = v;
        mx = fmaxf(mx, v);
    }
    __shared__ float red[256];
    red[tid] = mx;
    __syncthreads();
#pragma unroll
    for (int st = 128; st; st >>= 1) {
        if (tid < st) red[tid] = fmaxf(red[tid], red[tid + st]);
        __syncthreads();
    }
    mx = red[0];
    __syncthreads();

    float sum = 0.f;
#pragma unroll
    for (int u = 0; u < 8; ++u) {
        vals[u] = __expf(vals[u] - mx);
        sum += vals[u];
    }
    red[tid] = sum;
    __syncthreads();
#pragma unroll
    for (int st = 128; st; st >>= 1) {
        if (tid < st) red[tid] += red[tid + st];
        __syncthreads();
    }
    const float inv = 1.f / red[0];
#pragma unroll
    for (int u = 0; u < 8; ++u) p[tid + u * 256] = vals[u] * inv;
}

__global__ void copy_x_kernel(const float* __restrict__ x, float* __restrict__ rinraw)
{
    const long i = (long)blockIdx.x * 256 + threadIdx.x;
    const long row = i >> 7;
    const long col = i & 127;
    ((float4*)rinraw)[row * (2 * DD / 4) + col] = ((const float4*)x)[i];
}

__global__ void init_kernel()
{
    const int t = blockIdx.x * 256 + threadIdx.x;
    float* h = &g_h[0][0][0];
    if (t < 2 * 2 * BB * HH) h[t] = 0.f;
    if (t < 2) g_bar[t] = 0u;
}

// =====================================================================
// Persistent bidirectional GRU, v2:
//  - fma.rn.f32x2 packed dots (2 MAC/instr)
//  - xw for step t+1 prefetched during step t
//  - early arrive: hcat stores AFTER barrier arrival
//  - tid0-only threadfence + atomicAdd arrive; tight ld.acquire poll
// 128 CTAs = 2 dirs x 64 slices x 8 warps; warp owns one hidden column.
// =====================================================================
#define CPB 64

__global__ void __launch_bounds__(256, 1)
gru_kernel(const float* __restrict__ xw_f, const float* __restrict__ xw_b,
           const float* __restrict__ Whh_f, const float* __restrict__ Whh_b,
           const float* __restrict__ bhh_f, const float* __restrict__ bhh_b,
           float* __restrict__ hcat)
{
    const int cta = blockIdx.x;
    const int dir = cta >> 6;
    const int slice = cta & 63;
    const float* xw  = dir ? xw_b  : xw_f;
    const float* Whh = dir ? Whh_b : Whh_f;
    const float* bhh = dir ? bhh_b : bhh_f;

    const int tid = threadIdx.x;
    const int w = tid >> 5;
    const int lane = tid & 31;
    const int j = slice * 8 + w;

    // pinned weights as packed f32x2 pairs: lane owns elems {2*lane+64u, +1}
    unsigned long long wr2[8], wz2[8], wn2[8];
#pragma unroll
    for (int u = 0; u < 8; ++u) {
        wr2[u] = *(const unsigned long long*)&Whh[(long)(j)          * HH + 2 * lane + 64 * u];
        wz2[u] = *(const unsigned long long*)&Whh[(long)(HH + j)     * HH + 2 * lane + 64 * u];
        wn2[u] = *(const unsigned long long*)&Whh[(long)(2 * HH + j) * HH + 2 * lane + 64 * u];
    }
    const float br = bhh[j], bz = bhh[HH + j], bnb = bhh[2 * HH + j];

    __shared__ float h_s[BB * HH];            // 16 KB
    unsigned* bar = &g_bar[dir];

    // prefetch xw for step 0
    float xr[BB], xz[BB], xn[BB];
    {
        const int t0 = dir ? (SS - 1) : 0;
#pragma unroll
        for (int b = 0; b < BB; ++b) {
            const float* row = xw + (long)(b * SS + t0) * (3 * HH);
            xr[b] = __ldg(row + j);
            xz[b] = __ldg(row + HH + j);
            xn[b] = __ldg(row + 2 * HH + j);
        }
    }

    for (int step = 0; step < SS; ++step) {
        const int p = step & 1;
        const int tt = dir ? (SS - 1 - step) : step;

        if (step > 0) {
            if (tid == 0) {
                const unsigned target = (unsigned)(CPB * step);
                unsigned v;
                do {
                    asm volatile("ld.acquire.gpu.u32 %0, [%1];" : "=r"(v) : "l"(bar));
                } while (v < target);
            }
            __syncthreads();
        }

        // load previous h into smem (L2-coherent loads)
        {
            const float4* src = (const float4*)(&g_h[p][dir][0]);
            for (int i2 = tid; i2 < (BB * HH) / 4; i2 += 256)
                ((float4*)h_s)[i2] = __ldcg(src + i2);
        }
        __syncthreads();

        float hout[BB];
#pragma unroll
        for (int b = 0; b < BB; ++b) {
            const unsigned long long* hb2 =
                (const unsigned long long*)(h_s + b * HH) + lane;
            unsigned long long ar2 = 0ULL, az2 = 0ULL, an2 = 0ULL;
#pragma unroll
            for (int u = 0; u < 8; ++u) {
                const unsigned long long hv = hb2[32 * u];
                asm("fma.rn.f32x2 %0, %1, %2, %0;" : "+l"(ar2) : "l"(wr2[u]), "l"(hv));
                asm("fma.rn.f32x2 %0, %1, %2, %0;" : "+l"(az2) : "l"(wz2[u]), "l"(hv));
                asm("fma.rn.f32x2 %0, %1, %2, %0;" : "+l"(an2) : "l"(wn2[u]), "l"(hv));
            }
            float l0, h0, l1, h1, l2, h2;
            asm("mov.b64 {%0,%1}, %2;" : "=f"(l0), "=f"(h0) : "l"(ar2));
            asm("mov.b64 {%0,%1}, %2;" : "=f"(l1), "=f"(h1) : "l"(az2));
            asm("mov.b64 {%0,%1}, %2;" : "=f"(l2), "=f"(h2) : "l"(an2));
            float ar = l0 + h0, az = l1 + h1, an = l2 + h2;
#pragma unroll
            for (int off = 16; off; off >>= 1) {
                ar += __shfl_xor_sync(0xffffffffu, ar, off);
                az += __shfl_xor_sync(0xffffffffu, az, off);
                an += __shfl_xor_sync(0xffffffffu, an, off);
            }
            if (lane == 0) {
                const float hprev = h_s[b * HH + j];
                const float r = 1.f / (1.f + __expf(-(xr[b] + ar + br)));
                const float z = 1.f / (1.f + __expf(-(xz[b] + az + bz)));
                const float n = tanhf(xn[b] + r * (an + bnb));
                const float hn = (1.f - z) * n + z * hprev;
                g_h[p ^ 1][dir][b * HH + j] = hn;
                hout[b] = hn;
            }
        }

        // arrive (release: tid0 fence covers CTA's stores via syncthreads)
        __syncthreads();
        if (tid == 0) {
            __threadfence();
            atomicAdd(bar, 1u);
        }

        // off the critical path: hcat stores + next-step xw prefetch
        if (lane == 0) {
#pragma unroll
            for (int b = 0; b < BB; ++b)
                hcat[(long)(b * SS + tt) * (2 * HH) + dir * HH + j] = hout[b];
        }
        if (step + 1 < SS) {
            const int tn_ = dir ? (SS - 2 - step) : (step + 1);
#pragma unroll
            for (int b = 0; b < BB; ++b) {
                const float* row = xw + (long)(b * SS + tn_) * (3 * HH);
                xr[b] = __ldg(row + j);
                xz[b] = __ldg(row + HH + j);
                xn[b] = __ldg(row + 2 * HH + j);
            }
        }
    }
}

// =====================================================================
extern "C" void kernel_launch(void* const* d_in, const int* in_sizes, int n_in,
                              void* d_out, int out_size)
{
    (void)in_sizes; (void)n_in; (void)out_size;
    const float* x     = (const float*)d_in[0];
    const float* W     = (const float*)d_in[1];
    const float* Wg    = (const float*)d_in[2];
    const float* Wih_f = (const float*)d_in[3];
    const float* Whh_f = (const float*)d_in[4];
    const float* bih_f = (const float*)d_in[5];
    const float* bhh_f = (const float*)d_in[6];
    const float* Wih_b = (const float*)d_in[7];
    const float* Whh_b = (const float*)d_in[8];
    const float* bih_b = (const float*)d_in[9];
    const float* bhh_b = (const float*)d_in[10];
    const float* Wp    = (const float*)d_in[11];
    const float* bp    = (const float*)d_in[12];
    float* out = (float*)d_out;

    float *Wx, *sc, *rinraw, *rin, *xwf, *xwb, *hcat;
    cudaGetSymbolAddress((void**)&Wx,     g_Wx);
    cudaGetSymbolAddress((void**)&sc,     g_sc);
    cudaGetSymbolAddress((void**)&rinraw, g_rinraw);
    cudaGetSymbolAddress((void**)&rin,    g_rin);
    cudaGetSymbolAddress((void**)&xwf,    g_xwf);
    cudaGetSymbolAddress((void**)&xwb,    g_xwb);
    cudaGetSymbolAddress((void**)&hcat,   g_hcat);

    const int M = BB * SS;
    const int SMEM = 98304;   // 96 KB: 2-stage (A 16KB + B 32KB)

    cudaFuncSetAttribute(mma_gemm<1, 0>, cudaFuncAttributeMaxDynamicSharedMemorySize, SMEM);
    cudaFuncSetAttribute(mma_gemm<0, 1>, cudaFuncAttributeMaxDynamicSharedMemorySize, SMEM);
    cudaFuncSetAttribute(mma_gemm<0, 2>, cudaFuncAttributeMaxDynamicSharedMemorySize, SMEM);
    cudaFuncSetAttribute(mma_gemm<0, 3>, cudaFuncAttributeMaxDynamicSharedMemorySize, SMEM);

    init_kernel<<<64, 256>>>();

    // Wx = x @ W^T (fp32, feeds softmax logits)
    gemm128<<<dim3(DD / 128, M / 128, 1), 256>>>(
        x, W, Wx, M, DD, DD, DD, DD, DD, 0, 0, 0);

    // s[b] = Wx[b] @ x[b]^T (fp32, softmax logits)
    gemm128<<<dim3(SS / 128, SS / 128, BB), 256>>>(
        Wx, x, sc, SS, SS, DD, DD, DD, SS,
        (long)SS * DD, (long)SS * DD, (long)SS * SS);

    softmax_kernel<<<M, 256>>>(sc);

    copy_x_kernel<<<(M * DD / 4) / 256, 256>>>(x, rinraw);

    // rin_raw[:, 512:] = a[b] @ x[b]   (tf32 mma, BMODE1)  N=512 -> grid.x=2
    mma_gemm<1, 0><<<dim3(DD / 256, SS / 128, BB), 512, SMEM>>>(
        sc, x, rinraw + DD, SS, DD, SS, SS, DD, 2 * DD,
        (long)SS * SS, (long)SS * DD, (long)SS * 2 * DD, nullptr, nullptr, 0);

    // rin = rin_raw * sigmoid(rin_raw @ Wg^T)   N=1024
    mma_gemm<0, 2><<<dim3(2 * DD / 256, M / 128, 1), 512, SMEM>>>(
        rinraw, Wg, rin, M, 2 * DD, 2 * DD, 2 * DD, 2 * DD, 2 * DD,
        0, 0, 0, nullptr, nullptr, 0);

    // xw = rin @ Wih^T + bih (both directions)   N=1536
    mma_gemm<0, 1><<<dim3(3 * HH / 256, M / 128, 1), 512, SMEM>>>(
        rin, Wih_f, xwf, M, 3 * HH, 2 * DD, 2 * DD, 2 * DD, 3 * HH,
        0, 0, 0, bih_f, nullptr, 0);
    mma_gemm<0, 1><<<dim3(3 * HH / 256, M / 128, 1), 512, SMEM>>>(
        rin, Wih_b, xwb, M, 3 * HH, 2 * DD, 2 * DD, 2 * DD, 3 * HH,
        0, 0, 0, bih_b, nullptr, 0);

    // bidirectional GRU -> hcat [M, 1024]
    gru_kernel<<<128, 256>>>(xwf, xwb, Whh_f, Whh_b, bhh_f, bhh_b, hcat);

    // out = x + hcat @ Wp^T + bp   N=512
    mma_gemm<0, 3><<<dim3(DD / 256, M / 128, 1), 512, SMEM>>>(
        hcat, Wp, out, M, DD, 2 * HH, 2 * HH, 2 * HH, DD,
        0, 0, 0, bp, x, DD);
}

// round 5
// speedup vs baseline: 1.5331x; 1.0500x over previous
#include <cuda_runtime.h>
#include <cstdint>

#define BB 8
#define SS 2048
#define DD 512
#define HH 512

// ---------------- scratch (device globals; no cudaMalloc allowed) ----------------
__device__ float g_Wx[(size_t)BB * SS * DD];          //  32 MB
__device__ float g_sc[(size_t)BB * SS * SS];          // 134 MB
__device__ float g_rinraw[(size_t)BB * SS * 2 * DD];  //  64 MB
__device__ float g_rin[(size_t)BB * SS * 2 * DD];     //  64 MB
__device__ float g_xwf[(size_t)BB * SS * 3 * HH];     //  96 MB
__device__ float g_xwb[(size_t)BB * SS * 3 * HH];     //  96 MB
__device__ float g_hcat[(size_t)BB * SS * 2 * HH];    //  64 MB
__device__ float g_h[2][2][BB * HH];                  // double-buffered hidden state
__device__ unsigned g_bar[2];                         // per-direction barrier counters

// =====================================================================
// tf32 helpers
// =====================================================================
__device__ __forceinline__ uint32_t f2tf(float f) {
    uint32_t u; asm("cvt.rna.tf32.f32 %0, %1;" : "=r"(u) : "f"(f)); return u;
}
__device__ __forceinline__ void mma_tf32(float* c, const uint32_t* a, uint32_t b0, uint32_t b1) {
    asm volatile(
        "mma.sync.aligned.m16n8k8.row.col.f32.tf32.tf32.f32 "
        "{%0,%1,%2,%3}, {%4,%5,%6,%7}, {%8,%9}, {%0,%1,%2,%3};\n"
        : "+f"(c[0]), "+f"(c[1]), "+f"(c[2]), "+f"(c[3])
        : "r"(a[0]), "r"(a[1]), "r"(a[2]), "r"(a[3]), "r"(b0), "r"(b1));
}
__device__ __forceinline__ uint32_t smem_u32(const void* p) {
    uint32_t a;
    asm("{ .reg .u64 t; cvta.to.shared.u64 t, %1; cvt.u32.u64 %0, t; }" : "=r"(a) : "l"(p));
    return a;
}
#define CP_ASYNC16(dst, src) \
    asm volatile("cp.async.cg.shared.global [%0], [%1], 16;" :: "r"(dst), "l"(src))
#define CP_COMMIT() asm volatile("cp.async.commit_group;" ::: "memory")
#define CP_WAIT1()  asm volatile("cp.async.wait_group 1;" ::: "memory")

// =====================================================================
// tf32 mma.sync GEMM with 3-stage cp.async pipeline.
//   C[M,N] = A[M,K] @ op(B)  (+ epilogue)
//   BMODE 0: B [N,K] row-major   BMODE 1: B [K,N] row-major
//   SPLIT 1: 2-term tf32 operand split (3 mma terms) for ~fp32 accuracy
//   EPI 0 none / 1 +bias / 2 C=A[m,n]*sigmoid(acc) (N==K) / 3 +bias+R
// CTA: 128x128x32 tile, 256 threads, 8 warps (2m x 4n), warp tile 64x32.
// Stages: 3 x (A 16KB + B 16KB) = 96KB smem. All dims %128, K%32 == 0.
// =====================================================================
template <int BMODE, int SPLIT, int EPI>
__global__ void
#if 1
__launch_bounds__(256, SPLIT ? 1 : 2)
#endif
pip_gemm(const float* __restrict__ A, const float* __restrict__ B,
         float* __restrict__ C, int M, int N, int K,
         int lda, int ldb, int ldc,
         long sA, long sB, long sC,
         const float* __restrict__ bias,
         const float* __restrict__ R, int ldr)
{
    A += (long)blockIdx.z * sA;
    B += (long)blockIdx.z * sB;
    C += (long)blockIdx.z * sC;

    extern __shared__ float sm[];          // 3 stages x 8192 floats
    const uint32_t sbase = smem_u32(sm);

    const int tid  = threadIdx.x;
    const int lane = tid & 31;
    const int warp = tid >> 5;
    const int gid  = lane >> 2;
    const int tig  = lane & 3;
    const int wm   = (warp >> 2) * 64;
    const int wn   = (warp & 3) * 32;
    const int bm   = blockIdx.y * 128;
    const int bn   = blockIdx.x * 128;
    const int nk   = K >> 5;

    float acc[4][4][4];
#pragma unroll
    for (int mt = 0; mt < 4; ++mt)
#pragma unroll
        for (int nt = 0; nt < 4; ++nt)
#pragma unroll
            for (int q = 0; q < 4; ++q) acc[mt][nt][q] = 0.f;

    int b1off0[4], b1off1[4];
    if (BMODE == 1) {
#pragma unroll
        for (int nt = 0; nt < 4; ++nt) {
            const int n = wn + nt * 8 + gid;
            b1off0[nt] = tig * 128       + ((((n >> 2) ^ (tig << 2)) << 2) + (n & 3));
            b1off1[nt] = (tig + 4) * 128 + ((((n >> 2) ^ ((tig + 4) << 2)) << 2) + (n & 3));
        }
    }

    // per-thread copy coordinates (same swizzle as verified R2/R3 kernels)
    const int arow = tid >> 3, ac4 = tid & 7;                 // + 32*i rows

    // issue cp.async for k-tile kt into stage kt%3 (empty commit past end)
#define ISSUE(kt)                                                             \
    {                                                                         \
        if ((kt) < nk) {                                                      \
            const uint32_t sa = sbase + ((kt) % 3) * 32768;                   \
            const uint32_t sb = sa + 16384;                                   \
            _Pragma("unroll")                                                 \
            for (int i = 0; i < 4; ++i) {                                     \
                const int row = arow + 32 * i;                                \
                const uint32_t dst = sa + (uint32_t)(row * 32 + ((ac4 ^ (row & 7)) << 2)) * 4; \
                CP_ASYNC16(dst, A + (size_t)(bm + row) * lda + (kt) * 32 + ac4 * 4); \
            }                                                                 \
            if (BMODE == 0) {                                                 \
                _Pragma("unroll")                                             \
                for (int i = 0; i < 4; ++i) {                                 \
                    const int row = arow + 32 * i;                            \
                    const uint32_t dst = sb + (uint32_t)(row * 32 + ((ac4 ^ (row & 7)) << 2)) * 4; \
                    CP_ASYNC16(dst, B + (size_t)(bn + row) * ldb + (kt) * 32 + ac4 * 4); \
                }                                                             \
            } else {                                                          \
                _Pragma("unroll")                                             \
                for (int i = 0; i < 4; ++i) {                                 \
                    const int idx = tid + 256 * i;                            \
                    const int row = idx >> 5, c4 = idx & 31;                  \
                    const uint32_t dst = sb + (uint32_t)(row * 128 + ((c4 ^ ((row & 7) << 2)) << 2)) * 4; \
                    CP_ASYNC16(dst, B + (size_t)((kt) * 32 + row) * ldb + bn + c4 * 4); \
                }                                                             \
            }                                                                 \
        }                                                                     \
        CP_COMMIT();                                                          \
    }

    ISSUE(0);
    ISSUE(1);

    for (int kt = 0; kt < nk; ++kt) {
        CP_WAIT1();
        __syncthreads();            // stage kt ready; all warps done with stage kt-1

        const float* pa = sm + (kt % 3) * 8192;
        const float* pb = pa + 4096;

#pragma unroll
        for (int ks = 0; ks < 4; ++ks) {
            const int s0 = tig + (((2 * ks)     ^ gid) << 2);
            const int s1 = tig + (((2 * ks + 1) ^ gid) << 2);

            float af[4][4];
#pragma unroll
            for (int mt = 0; mt < 4; ++mt) {
                const int r0 = (wm + mt * 16 + gid) * 32;
                const int r1 = r0 + 256;
                af[mt][0] = pa[r0 + s0];
                af[mt][1] = pa[r1 + s0];
                af[mt][2] = pa[r0 + s1];
                af[mt][3] = pa[r1 + s1];
            }
            float bf[4][2];
#pragma unroll
            for (int nt = 0; nt < 4; ++nt) {
                if (BMODE == 0) {
                    const int nrow = (wn + nt * 8 + gid) * 32;
                    bf[nt][0] = pb[nrow + s0];
                    bf[nt][1] = pb[nrow + s1];
                } else {
                    bf[nt][0] = pb[b1off0[nt] + ks * 1024];
                    bf[nt][1] = pb[b1off1[nt] + ks * 1024];
                }
            }

            if (!SPLIT) {
                uint32_t ah[4][4], bh[4][2];
#pragma unroll
                for (int mt = 0; mt < 4; ++mt)
#pragma unroll
                    for (int q = 0; q < 4; ++q) ah[mt][q] = f2tf(af[mt][q]);
#pragma unroll
                for (int nt = 0; nt < 4; ++nt) {
                    bh[nt][0] = f2tf(bf[nt][0]);
                    bh[nt][1] = f2tf(bf[nt][1]);
                }
#pragma unroll
                for (int mt = 0; mt < 4; ++mt)
#pragma unroll
                    for (int nt = 0; nt < 4; ++nt)
                        mma_tf32(acc[mt][nt], ah[mt], bh[nt][0], bh[nt][1]);
            } else {
                uint32_t ah[4][4], al[4][4], bh[4][2], bl[4][2];
#pragma unroll
                for (int mt = 0; mt < 4; ++mt)
#pragma unroll
                    for (int q = 0; q < 4; ++q) {
                        const uint32_t h = f2tf(af[mt][q]);
                        ah[mt][q] = h;
                        al[mt][q] = f2tf(af[mt][q] - __uint_as_float(h));
                    }
#pragma unroll
                for (int nt = 0; nt < 4; ++nt)
#pragma unroll
                    for (int q = 0; q < 2; ++q) {
                        const uint32_t h = f2tf(bf[nt][q]);
                        bh[nt][q] = h;
                        bl[nt][q] = f2tf(bf[nt][q] - __uint_as_float(h));
                    }
#pragma unroll
                for (int mt = 0; mt < 4; ++mt)
#pragma unroll
                    for (int nt = 0; nt < 4; ++nt) {
                        mma_tf32(acc[mt][nt], al[mt], bh[nt][0], bh[nt][1]);
                        mma_tf32(acc[mt][nt], ah[mt], bl[nt][0], bl[nt][1]);
                        mma_tf32(acc[mt][nt], ah[mt], bh[nt][0], bh[nt][1]);
                    }
            }
        }
        ISSUE(kt + 2);
    }
#undef ISSUE

    // ---- epilogue ----
#pragma unroll
    for (int mt = 0; mt < 4; ++mt) {
#pragma unroll
        for (int half = 0; half < 2; ++half) {
            const long row = bm + wm + mt * 16 + gid + half * 8;
#pragma unroll
            for (int nt = 0; nt < 4; ++nt) {
                const int col = bn + wn + nt * 8 + 2 * tig;
                float v0 = acc[mt][nt][half * 2 + 0];
                float v1 = acc[mt][nt][half * 2 + 1];
                if (EPI == 1 || EPI == 3) {
                    v0 += bias[col];
                    v1 += bias[col + 1];
                }
                if (EPI == 3) {
                    const float2 rr = *(const float2*)&R[row * ldr + col];
                    v0 += rr.x; v1 += rr.y;
                }
                if (EPI == 2) {
                    const float2 av = *(const float2*)&A[row * (size_t)lda + col];
                    v0 = av.x * (1.f / (1.f + __expf(-v0)));
                    v1 = av.y * (1.f / (1.f + __expf(-v1)));
                }
                float2 o; o.x = v0; o.y = v1;
                *(float2*)&C[row * (size_t)ldc + col] = o;
            }
        }
    }
}

// =====================================================================
// Row softmax over [B*S, S] with diagonal mask
// =====================================================================
__global__ void softmax_kernel(float* __restrict__ s)
{
    const long row = blockIdx.x;
    const int i = (int)(row & (SS - 1));
    float* p = s + row * SS;
    const int tid = threadIdx.x;

    float vals[8];
    float mx = -1e30f;
#pragma unroll
    for (int u = 0; u < 8; ++u) {
        const int j = tid + u * 256;
        float v = p[j];
        if (j == i) v = -INFINITY;
        vals[u] = v;
        mx = fmaxf(mx, v);
    }
    __shared__ float red[256];
    red[tid] = mx;
    __syncthreads();
#pragma unroll
    for (int st = 128; st; st >>= 1) {
        if (tid < st) red[tid] = fmaxf(red[tid], red[tid + st]);
        __syncthreads();
    }
    mx = red[0];
    __syncthreads();

    float sum = 0.f;
#pragma unroll
    for (int u = 0; u < 8; ++u) {
        vals[u] = __expf(vals[u] - mx);
        sum += vals[u];
    }
    red[tid] = sum;
    __syncthreads();
#pragma unroll
    for (int st = 128; st; st >>= 1) {
        if (tid < st) red[tid] += red[tid + st];
        __syncthreads();
    }
    const float inv = 1.f / red[0];
#pragma unroll
    for (int u = 0; u < 8; ++u) p[tid + u * 256] = vals[u] * inv;
}

__global__ void copy_x_kernel(const float* __restrict__ x, float* __restrict__ rinraw)
{
    const long i = (long)blockIdx.x * 256 + threadIdx.x;
    const long row = i >> 7;
    const long col = i & 127;
    ((float4*)rinraw)[row * (2 * DD / 4) + col] = ((const float4*)x)[i];
}

__global__ void init_kernel()
{
    const int t = blockIdx.x * 256 + threadIdx.x;
    float* h = &g_h[0][0][0];
    if (t < 2 * 2 * BB * HH) h[t] = 0.f;
    if (t < 2) g_bar[t] = 0u;
}

// =====================================================================
// Persistent bidirectional GRU (v2, unchanged from R3)
// =====================================================================
#define CPB 64

__global__ void __launch_bounds__(256, 1)
gru_kernel(const float* __restrict__ xw_f, const float* __restrict__ xw_b,
           const float* __restrict__ Whh_f, const float* __restrict__ Whh_b,
           const float* __restrict__ bhh_f, const float* __restrict__ bhh_b,
           float* __restrict__ hcat)
{
    const int cta = blockIdx.x;
    const int dir = cta >> 6;
    const int slice = cta & 63;
    const float* xw  = dir ? xw_b  : xw_f;
    const float* Whh = dir ? Whh_b : Whh_f;
    const float* bhh = dir ? bhh_b : bhh_f;

    const int tid = threadIdx.x;
    const int w = tid >> 5;
    const int lane = tid & 31;
    const int j = slice * 8 + w;

    unsigned long long wr2[8], wz2[8], wn2[8];
#pragma unroll
    for (int u = 0; u < 8; ++u) {
        wr2[u] = *(const unsigned long long*)&Whh[(long)(j)          * HH + 2 * lane + 64 * u];
        wz2[u] = *(const unsigned long long*)&Whh[(long)(HH + j)     * HH + 2 * lane + 64 * u];
        wn2[u] = *(const unsigned long long*)&Whh[(long)(2 * HH + j) * HH + 2 * lane + 64 * u];
    }
    const float br = bhh[j], bz = bhh[HH + j], bnb = bhh[2 * HH + j];

    __shared__ float h_s[BB * HH];
    unsigned* bar = &g_bar[dir];

    float xr[BB], xz[BB], xn[BB];
    {
        const int t0 = dir ? (SS - 1) : 0;
#pragma unroll
        for (int b = 0; b < BB; ++b) {
            const float* row = xw + (long)(b * SS + t0) * (3 * HH);
            xr[b] = __ldg(row + j);
            xz[b] = __ldg(row + HH + j);
            xn[b] = __ldg(row + 2 * HH + j);
        }
    }

    for (int step = 0; step < SS; ++step) {
        const int p = step & 1;
        const int tt = dir ? (SS - 1 - step) : step;

        if (step > 0) {
            if (tid == 0) {
                const unsigned target = (unsigned)(CPB * step);
                unsigned v;
                do {
                    asm volatile("ld.acquire.gpu.u32 %0, [%1];" : "=r"(v) : "l"(bar));
                } while (v < target);
            }
            __syncthreads();
        }

        {
            const float4* src = (const float4*)(&g_h[p][dir][0]);
            for (int i2 = tid; i2 < (BB * HH) / 4; i2 += 256)
                ((float4*)h_s)[i2] = __ldcg(src + i2);
        }
        __syncthreads();

        float hout[BB];
#pragma unroll
        for (int b = 0; b < BB; ++b) {
            const unsigned long long* hb2 =
                (const unsigned long long*)(h_s + b * HH) + lane;
            unsigned long long ar2 = 0ULL, az2 = 0ULL, an2 = 0ULL;
#pragma unroll
            for (int u = 0; u < 8; ++u) {
                const unsigned long long hv = hb2[32 * u];
                asm("fma.rn.f32x2 %0, %1, %2, %0;" : "+l"(ar2) : "l"(wr2[u]), "l"(hv));
                asm("fma.rn.f32x2 %0, %1, %2, %0;" : "+l"(az2) : "l"(wz2[u]), "l"(hv));
                asm("fma.rn.f32x2 %0, %1, %2, %0;" : "+l"(an2) : "l"(wn2[u]), "l"(hv));
            }
            float l0, h0, l1, h1, l2, h2;
            asm("mov.b64 {%0,%1}, %2;" : "=f"(l0), "=f"(h0) : "l"(ar2));
            asm("mov.b64 {%0,%1}, %2;" : "=f"(l1), "=f"(h1) : "l"(az2));
            asm("mov.b64 {%0,%1}, %2;" : "=f"(l2), "=f"(h2) : "l"(an2));
            float ar = l0 + h0, az = l1 + h1, an = l2 + h2;
#pragma unroll
            for (int off = 16; off; off >>= 1) {
                ar += __shfl_xor_sync(0xffffffffu, ar, off);
                az += __shfl_xor_sync(0xffffffffu, az, off);
                an += __shfl_xor_sync(0xffffffffu, an, off);
            }
            if (lane == 0) {
                const float hprev = h_s[b * HH + j];
                const float r = 1.f / (1.f + __expf(-(xr[b] + ar + br)));
                const float z = 1.f / (1.f + __expf(-(xz[b] + az + bz)));
                const float n = tanhf(xn[b] + r * (an + bnb));
                const float hn = (1.f - z) * n + z * hprev;
                g_h[p ^ 1][dir][b * HH + j] = hn;
                hout[b] = hn;
            }
        }

        __syncthreads();
        if (tid == 0) {
            __threadfence();
            atomicAdd(bar, 1u);
        }

        if (lane == 0) {
#pragma unroll
            for (int b = 0; b < BB; ++b)
                hcat[(long)(b * SS + tt) * (2 * HH) + dir * HH + j] = hout[b];
        }
        if (step + 1 < SS) {
            const int tn_ = dir ? (SS - 2 - step) : (step + 1);
#pragma unroll
            for (int b = 0; b < BB; ++b) {
                const float* row = xw + (long)(b * SS + tn_) * (3 * HH);
                xr[b] = __ldg(row + j);
                xz[b] = __ldg(row + HH + j);
                xn[b] = __ldg(row + 2 * HH + j);
            }
        }
    }
}

// =====================================================================
extern "C" void kernel_launch(void* const* d_in, const int* in_sizes, int n_in,
                              void* d_out, int out_size)
{
    (void)in_sizes; (void)n_in; (void)out_size;
    const float* x     = (const float*)d_in[0];
    const float* W     = (const float*)d_in[1];
    const float* Wg    = (const float*)d_in[2];
    const float* Wih_f = (const float*)d_in[3];
    const float* Whh_f = (const float*)d_in[4];
    const float* bih_f = (const float*)d_in[5];
    const float* bhh_f = (const float*)d_in[6];
    const float* Wih_b = (const float*)d_in[7];
    const float* Whh_b = (const float*)d_in[8];
    const float* bih_b = (const float*)d_in[9];
    const float* bhh_b = (const float*)d_in[10];
    const float* Wp    = (const float*)d_in[11];
    const float* bp    = (const float*)d_in[12];
    float* out = (float*)d_out;

    float *Wx, *sc, *rinraw, *rin, *xwf, *xwb, *hcat;
    cudaGetSymbolAddress((void**)&Wx,     g_Wx);
    cudaGetSymbolAddress((void**)&sc,     g_sc);
    cudaGetSymbolAddress((void**)&rinraw, g_rinraw);
    cudaGetSymbolAddress((void**)&rin,    g_rin);
    cudaGetSymbolAddress((void**)&xwf,    g_xwf);
    cudaGetSymbolAddress((void**)&xwb,    g_xwb);
    cudaGetSymbolAddress((void**)&hcat,   g_hcat);

    const int M = BB * SS;
    const int SMEM = 98304;   // 3 stages x 32KB

    cudaFuncSetAttribute(pip_gemm<0, 1, 0>, cudaFuncAttributeMaxDynamicSharedMemorySize, SMEM);
    cudaFuncSetAttribute(pip_gemm<1, 0, 0>, cudaFuncAttributeMaxDynamicSharedMemorySize, SMEM);
    cudaFuncSetAttribute(pip_gemm<0, 0, 1>, cudaFuncAttributeMaxDynamicSharedMemorySize, SMEM);
    cudaFuncSetAttribute(pip_gemm<0, 0, 2>, cudaFuncAttributeMaxDynamicSharedMemorySize, SMEM);
    cudaFuncSetAttribute(pip_gemm<0, 0, 3>, cudaFuncAttributeMaxDynamicSharedMemorySize, SMEM);

    init_kernel<<<64, 256>>>();

    // rin_raw[:, :512] = x (moved early; also shifts ncu capture window)
    copy_x_kernel<<<(M * DD / 4) / 256, 256>>>(x, rinraw);

    // Wx = x @ W^T (split-tf32: feeds softmax logits)
    pip_gemm<0, 1, 0><<<dim3(DD / 128, M / 128, 1), 256, SMEM>>>(
        x, W, Wx, M, DD, DD, DD, DD, DD, 0, 0, 0, nullptr, nullptr, 0);

    // s[b] = Wx[b] @ x[b]^T (split-tf32 logits)
    pip_gemm<0, 1, 0><<<dim3(SS / 128, SS / 128, BB), 256, SMEM>>>(
        Wx, x, sc, SS, SS, DD, DD, DD, SS,
        (long)SS * DD, (long)SS * DD, (long)SS * SS, nullptr, nullptr, 0);

    softmax_kernel<<<M, 256>>>(sc);

    // rin_raw[:, 512:] = a[b] @ x[b]   (tf32, BMODE1)
    pip_gemm<1, 0, 0><<<dim3(DD / 128, SS / 128, BB), 256, SMEM>>>(
        sc, x, rinraw + DD, SS, DD, SS, SS, DD, 2 * DD,
        (long)SS * SS, (long)SS * DD, (long)SS * 2 * DD, nullptr, nullptr, 0);

    // rin = rin_raw * sigmoid(rin_raw @ Wg^T)
    pip_gemm<0, 0, 2><<<dim3(2 * DD / 128, M / 128, 1), 256, SMEM>>>(
        rinraw, Wg, rin, M, 2 * DD, 2 * DD, 2 * DD, 2 * DD, 2 * DD,
        0, 0, 0, nullptr, nullptr, 0);

    // xw = rin @ Wih^T + bih (both directions)
    pip_gemm<0, 0, 1><<<dim3(3 * HH / 128, M / 128, 1), 256, SMEM>>>(
        rin, Wih_f, xwf, M, 3 * HH, 2 * DD, 2 * DD, 2 * DD, 3 * HH,
        0, 0, 0, bih_f, nullptr, 0);
    pip_gemm<0, 0, 1><<<dim3(3 * HH / 128, M / 128, 1), 256, SMEM>>>(
        rin, Wih_b, xwb, M, 3 * HH, 2 * DD, 2 * DD, 2 * DD, 3 * HH,
        0, 0, 0, bih_b, nullptr, 0);

    // bidirectional GRU -> hcat [M, 1024]
    gru_kernel<<<128, 256>>>(xwf, xwb, Whh_f, Whh_b, bhh_f, bhh_b, hcat);

    // out = x + hcat @ Wp^T + bp
    pip_gemm<0, 0, 3><<<dim3(DD / 128, M / 128, 1), 256, SMEM>>>(
        hcat, Wp, out, M, DD, 2 * HH, 2 * HH, 2 * HH, DD,
        0, 0, 0, bp, x, DD);
}

// round 7
// speedup vs baseline: 1.5832x; 1.0327x over previous
#include <cuda_runtime.h>
#include <cstdint>

#define BB 8
#define SS 2048
#define DD 512
#define HH 512

// ---------------- scratch (device globals; no cudaMalloc allowed) ----------------
__device__ float g_Wx[(size_t)BB * SS * DD];          //  32 MB
__device__ float g_sc[(size_t)BB * SS * SS];          // 134 MB
__device__ float g_rinraw[(size_t)BB * SS * 2 * DD];  //  64 MB
__device__ float g_rin[(size_t)BB * SS * 2 * DD];     //  64 MB
__device__ float g_xwf[(size_t)BB * SS * 3 * HH];     //  96 MB
__device__ float g_xwb[(size_t)BB * SS * 3 * HH];     //  96 MB
__device__ float g_hcat[(size_t)BB * SS * 2 * HH];    //  64 MB
__device__ float g_h[2][2][BB * HH];                  // double-buffered hidden state
__device__ unsigned g_bar[2][8][32];                  // sharded barrier counters (128B apart)

// =====================================================================
// tf32 helpers
// =====================================================================
__device__ __forceinline__ uint32_t f2tf(float f) {
    uint32_t u; asm("cvt.rna.tf32.f32 %0, %1;" : "=r"(u) : "f"(f)); return u;
}
__device__ __forceinline__ void mma_tf32(float* c, const uint32_t* a, uint32_t b0, uint32_t b1) {
    asm volatile(
        "mma.sync.aligned.m16n8k8.row.col.f32.tf32.tf32.f32 "
        "{%0,%1,%2,%3}, {%4,%5,%6,%7}, {%8,%9}, {%0,%1,%2,%3};\n"
        : "+f"(c[0]), "+f"(c[1]), "+f"(c[2]), "+f"(c[3])
        : "r"(a[0]), "r"(a[1]), "r"(a[2]), "r"(a[3]), "r"(b0), "r"(b1));
}
__device__ __forceinline__ uint32_t smem_u32(const void* p) {
    uint32_t a;
    asm("{ .reg .u64 t; cvta.to.shared.u64 t, %1; cvt.u32.u64 %0, t; }" : "=r"(a) : "l"(p));
    return a;
}
#define CP_ASYNC16(dst, src) \
    asm volatile("cp.async.cg.shared.global [%0], [%1], 16;" :: "r"(dst), "l"(src))
#define CP_COMMIT() asm volatile("cp.async.commit_group;" ::: "memory")
#define CP_WAIT1()  asm volatile("cp.async.wait_group 1;" ::: "memory")

// =====================================================================
// tf32 mma.sync GEMM with 3-stage cp.async pipeline (unchanged from R5).
//   C[M,N] = A[M,K] @ op(B)  (+ epilogue)
//   BMODE 0: B [N,K] row-major   BMODE 1: B [K,N] row-major
//   SPLIT 1: 2-term tf32 operand split (3 mma terms) for ~fp32 accuracy
//   EPI 0 none / 1 +bias / 2 C=A[m,n]*sigmoid(acc) (N==K) / 3 +bias+R
// =====================================================================
template <int BMODE, int SPLIT, int EPI>
__global__ void
__launch_bounds__(256, SPLIT ? 1 : 2)
pip_gemm(const float* __restrict__ A, const float* __restrict__ B,
         float* __restrict__ C, int M, int N, int K,
         int lda, int ldb, int ldc,
         long sA, long sB, long sC,
         const float* __restrict__ bias,
         const float* __restrict__ R, int ldr)
{
    A += (long)blockIdx.z * sA;
    B += (long)blockIdx.z * sB;
    C += (long)blockIdx.z * sC;

    extern __shared__ float sm[];          // 3 stages x 8192 floats
    const uint32_t sbase = smem_u32(sm);

    const int tid  = threadIdx.x;
    const int lane = tid & 31;
    const int warp = tid >> 5;
    const int gid  = lane >> 2;
    const int tig  = lane & 3;
    const int wm   = (warp >> 2) * 64;
    const int wn   = (warp & 3) * 32;
    const int bm   = blockIdx.y * 128;
    const int bn   = blockIdx.x * 128;
    const int nk   = K >> 5;

    float acc[4][4][4];
#pragma unroll
    for (int mt = 0; mt < 4; ++mt)
#pragma unroll
        for (int nt = 0; nt < 4; ++nt)
#pragma unroll
            for (int q = 0; q < 4; ++q) acc[mt][nt][q] = 0.f;

    int b1off0[4], b1off1[4];
    if (BMODE == 1) {
#pragma unroll
        for (int nt = 0; nt < 4; ++nt) {
            const int n = wn + nt * 8 + gid;
            b1off0[nt] = tig * 128       + ((((n >> 2) ^ (tig << 2)) << 2) + (n & 3));
            b1off1[nt] = (tig + 4) * 128 + ((((n >> 2) ^ ((tig + 4) << 2)) << 2) + (n & 3));
        }
    }

    const int arow = tid >> 3, ac4 = tid & 7;

#define ISSUE(kt)                                                             \
    {                                                                         \
        if ((kt) < nk) {                                                      \
            const uint32_t sa = sbase + ((kt) % 3) * 32768;                   \
            const uint32_t sb = sa + 16384;                                   \
            _Pragma("unroll")                                                 \
            for (int i = 0; i < 4; ++i) {                                     \
                const int row = arow + 32 * i;                                \
                const uint32_t dst = sa + (uint32_t)(row * 32 + ((ac4 ^ (row & 7)) << 2)) * 4; \
                CP_ASYNC16(dst, A + (size_t)(bm + row) * lda + (kt) * 32 + ac4 * 4); \
            }                                                                 \
            if (BMODE == 0) {                                                 \
                _Pragma("unroll")                                             \
                for (int i = 0; i < 4; ++i) {                                 \
                    const int row = arow + 32 * i;                            \
                    const uint32_t dst = sb + (uint32_t)(row * 32 + ((ac4 ^ (row & 7)) << 2)) * 4; \
                    CP_ASYNC16(dst, B + (size_t)(bn + row) * ldb + (kt) * 32 + ac4 * 4); \
                }                                                             \
            } else {                                                          \
                _Pragma("unroll")                                             \
                for (int i = 0; i < 4; ++i) {                                 \
                    const int idx = tid + 256 * i;                            \
                    const int row = idx >> 5, c4 = idx & 31;                  \
                    const uint32_t dst = sb + (uint32_t)(row * 128 + ((c4 ^ ((row & 7) << 2)) << 2)) * 4; \
                    CP_ASYNC16(dst, B + (size_t)((kt) * 32 + row) * ldb + bn + c4 * 4); \
                }                                                             \
            }                                                                 \
        }                                                                     \
        CP_COMMIT();                                                          \
    }

    ISSUE(0);
    ISSUE(1);

    for (int kt = 0; kt < nk; ++kt) {
        CP_WAIT1();
        __syncthreads();

        const float* pa = sm + (kt % 3) * 8192;
        const float* pb = pa + 4096;

#pragma unroll
        for (int ks = 0; ks < 4; ++ks) {
            const int s0 = tig + (((2 * ks)     ^ gid) << 2);
            const int s1 = tig + (((2 * ks + 1) ^ gid) << 2);

            float af[4][4];
#pragma unroll
            for (int mt = 0; mt < 4; ++mt) {
                const int r0 = (wm + mt * 16 + gid) * 32;
                const int r1 = r0 + 256;
                af[mt][0] = pa[r0 + s0];
                af[mt][1] = pa[r1 + s0];
                af[mt][2] = pa[r0 + s1];
                af[mt][3] = pa[r1 + s1];
            }
            float bf[4][2];
#pragma unroll
            for (int nt = 0; nt < 4; ++nt) {
                if (BMODE == 0) {
                    const int nrow = (wn + nt * 8 + gid) * 32;
                    bf[nt][0] = pb[nrow + s0];
                    bf[nt][1] = pb[nrow + s1];
                } else {
                    bf[nt][0] = pb[b1off0[nt] + ks * 1024];
                    bf[nt][1] = pb[b1off1[nt] + ks * 1024];
                }
            }

            if (!SPLIT) {
                uint32_t ah[4][4], bh[4][2];
#pragma unroll
                for (int mt = 0; mt < 4; ++mt)
#pragma unroll
                    for (int q = 0; q < 4; ++q) ah[mt][q] = f2tf(af[mt][q]);
#pragma unroll
                for (int nt = 0; nt < 4; ++nt) {
                    bh[nt][0] = f2tf(bf[nt][0]);
                    bh[nt][1] = f2tf(bf[nt][1]);
                }
#pragma unroll
                for (int mt = 0; mt < 4; ++mt)
#pragma unroll
                    for (int nt = 0; nt < 4; ++nt)
                        mma_tf32(acc[mt][nt], ah[mt], bh[nt][0], bh[nt][1]);
            } else {
                uint32_t ah[4][4], al[4][4], bh[4][2], bl[4][2];
#pragma unroll
                for (int mt = 0; mt < 4; ++mt)
#pragma unroll
                    for (int q = 0; q < 4; ++q) {
                        const uint32_t h = f2tf(af[mt][q]);
                        ah[mt][q] = h;
                        al[mt][q] = f2tf(af[mt][q] - __uint_as_float(h));
                    }
#pragma unroll
                for (int nt = 0; nt < 4; ++nt)
#pragma unroll
                    for (int q = 0; q < 2; ++q) {
                        const uint32_t h = f2tf(bf[nt][q]);
                        bh[nt][q] = h;
                        bl[nt][q] = f2tf(bf[nt][q] - __uint_as_float(h));
                    }
#pragma unroll
                for (int mt = 0; mt < 4; ++mt)
#pragma unroll
                    for (int nt = 0; nt < 4; ++nt) {
                        mma_tf32(acc[mt][nt], al[mt], bh[nt][0], bh[nt][1]);
                        mma_tf32(acc[mt][nt], ah[mt], bl[nt][0], bl[nt][1]);
                        mma_tf32(acc[mt][nt], ah[mt], bh[nt][0], bh[nt][1]);
                    }
            }
        }
        ISSUE(kt + 2);
    }
#undef ISSUE

#pragma unroll
    for (int mt = 0; mt < 4; ++mt) {
#pragma unroll
        for (int half = 0; half < 2; ++half) {
            const long row = bm + wm + mt * 16 + gid + half * 8;
#pragma unroll
            for (int nt = 0; nt < 4; ++nt) {
                const int col = bn + wn + nt * 8 + 2 * tig;
                float v0 = acc[mt][nt][half * 2 + 0];
                float v1 = acc[mt][nt][half * 2 + 1];
                if (EPI == 1 || EPI == 3) {
                    v0 += bias[col];
                    v1 += bias[col + 1];
                }
                if (EPI == 3) {
                    const float2 rr = *(const float2*)&R[row * ldr + col];
                    v0 += rr.x; v1 += rr.y;
                }
                if (EPI == 2) {
                    const float2 av = *(const float2*)&A[row * (size_t)lda + col];
                    v0 = av.x * (1.f / (1.f + __expf(-v0)));
                    v1 = av.y * (1.f / (1.f + __expf(-v1)));
                }
                float2 o; o.x = v0; o.y = v1;
                *(float2*)&C[row * (size_t)ldc + col] = o;
            }
        }
    }
}

// =====================================================================
// Row softmax over [B*S, S] with diagonal mask
// =====================================================================
__global__ void softmax_kernel(float* __restrict__ s)
{
    const long row = blockIdx.x;
    const int i = (int)(row & (SS - 1));
    float* p = s + row * SS;
    const int tid = threadIdx.x;

    float vals[8];
    float mx = -1e30f;
#pragma unroll
    for (int u = 0; u < 8; ++u) {
        const int j = tid + u * 256;
        float v = p[j];
        if (j == i) v = -INFINITY;
        vals[u] = v;
        mx = fmaxf(mx, v);
    }
    __shared__ float red[256];
    red[tid] = mx;
    __syncthreads();
#pragma unroll
    for (int st = 128; st; st >>= 1) {
        if (tid < st) red[tid] = fmaxf(red[tid], red[tid + st]);
        __syncthreads();
    }
    mx = red[0];
    __syncthreads();

    float sum = 0.f;
#pragma unroll
    for (int u = 0; u < 8; ++u) {
        vals[u] = __expf(vals[u] - mx);
        sum += vals[u];
    }
    red[tid] = sum;
    __syncthreads();
#pragma unroll
    for (int st = 128; st; st >>= 1) {
        if (tid < st) red[tid] += red[tid + st];
        __syncthreads();
    }
    const float inv = 1.f / red[0];
#pragma unroll
    for (int u = 0; u < 8; ++u) p[tid + u * 256] = vals[u] * inv;
}

__global__ void copy_x_kernel(const float* __restrict__ x, float* __restrict__ rinraw)
{
    const long i = (long)blockIdx.x * 256 + threadIdx.x;
    const long row = i >> 7;
    const long col = i & 127;
    ((float4*)rinraw)[row * (2 * DD / 4) + col] = ((const float4*)x)[i];
}

__global__ void init_kernel()
{
    const int t = blockIdx.x * 256 + threadIdx.x;
    float* h = &g_h[0][0][0];
    if (t < 2 * 2 * BB * HH) h[t] = 0.f;
    unsigned* bar = &g_bar[0][0][0];
    if (t < 2 * 8 * 32) bar[t] = 0u;
}

// =====================================================================
// Persistent bidirectional GRU v3: sharded barrier.
// 64 CTAs/dir arrive on 8 sub-counters (8 arrivals each -> ~8x less
// L2-atomic serialization); 8 threads poll the 8 counters in parallel.
// =====================================================================
#define CPB 64

__global__ void __launch_bounds__(256, 1)
gru_kernel(const float* __restrict__ xw_f, const float* __restrict__ xw_b,
           const float* __restrict__ Whh_f, const float* __restrict__ Whh_b,
           const float* __restrict__ bhh_f, const float* __restrict__ bhh_b,
           float* __restrict__ hcat)
{
    const int cta = blockIdx.x;
    const int dir = cta >> 6;
    const int slice = cta & 63;
    const float* xw  = dir ? xw_b  : xw_f;
    const float* Whh = dir ? Whh_b : Whh_f;
    const float* bhh = dir ? bhh_b : bhh_f;

    const int tid = threadIdx.x;
    const int w = tid >> 5;
    const int lane = tid & 31;
    const int j = slice * 8 + w;

    unsigned long long wr2[8], wz2[8], wn2[8];
#pragma unroll
    for (int u = 0; u < 8; ++u) {
        wr2[u] = *(const unsigned long long*)&Whh[(long)(j)          * HH + 2 * lane + 64 * u];
        wz2[u] = *(const unsigned long long*)&Whh[(long)(HH + j)     * HH + 2 * lane + 64 * u];
        wn2[u] = *(const unsigned long long*)&Whh[(long)(2 * HH + j) * HH + 2 * lane + 64 * u];
    }
    const float br = bhh[j], bz = bhh[HH + j], bnb = bhh[2 * HH + j];

    __shared__ float h_s[BB * HH];
    unsigned* mycnt = &g_bar[dir][slice & 7][0];      // this CTA's arrival counter
    unsigned* pollcnt = (tid < 8) ? &g_bar[dir][tid][0] : nullptr;

    float xr[BB], xz[BB], xn[BB];
    {
        const int t0 = dir ? (SS - 1) : 0;
#pragma unroll
        for (int b = 0; b < BB; ++b) {
            const float* row = xw + (long)(b * SS + t0) * (3 * HH);
            xr[b] = __ldg(row + j);
            xz[b] = __ldg(row + HH + j);
            xn[b] = __ldg(row + 2 * HH + j);
        }
    }

    for (int step = 0; step < SS; ++step) {
        const int p = step & 1;
        const int tt = dir ? (SS - 1 - step) : step;

        if (step > 0) {
            if (tid < 8) {
                const unsigned target = (unsigned)((CPB / 8) * step);
                unsigned v;
                do {
                    asm volatile("ld.acquire.gpu.u32 %0, [%1];" : "=r"(v) : "l"(pollcnt));
                } while (v < target);
            }
            __syncthreads();
        }

        {
            const float4* src = (const float4*)(&g_h[p][dir][0]);
            for (int i2 = tid; i2 < (BB * HH) / 4; i2 += 256)
                ((float4*)h_s)[i2] = __ldcg(src + i2);
        }
        __syncthreads();

        float hout[BB];
#pragma unroll
        for (int b = 0; b < BB; ++b) {
            const unsigned long long* hb2 =
                (const unsigned long long*)(h_s + b * HH) + lane;
            unsigned long long ar2 = 0ULL, az2 = 0ULL, an2 = 0ULL;
#pragma unroll
            for (int u = 0; u < 8; ++u) {
                const unsigned long long hv = hb2[32 * u];
                asm("fma.rn.f32x2 %0, %1, %2, %0;" : "+l"(ar2) : "l"(wr2[u]), "l"(hv));
                asm("fma.rn.f32x2 %0, %1, %2, %0;" : "+l"(az2) : "l"(wz2[u]), "l"(hv));
                asm("fma.rn.f32x2 %0, %1, %2, %0;" : "+l"(an2) : "l"(wn2[u]), "l"(hv));
            }
            float l0, h0, l1, h1, l2, h2;
            asm("mov.b64 {%0,%1}, %2;" : "=f"(l0), "=f"(h0) : "l"(ar2));
            asm("mov.b64 {%0,%1}, %2;" : "=f"(l1), "=f"(h1) : "l"(az2));
            asm("mov.b64 {%0,%1}, %2;" : "=f"(l2), "=f"(h2) : "l"(an2));
            float ar = l0 + h0, az = l1 + h1, an = l2 + h2;
#pragma unroll
            for (int off = 16; off; off >>= 1) {
                ar += __shfl_xor_sync(0xffffffffu, ar, off);
                az += __shfl_xor_sync(0xffffffffu, az, off);
                an += __shfl_xor_sync(0xffffffffu, an, off);
            }
            if (lane == 0) {
                const float hprev = h_s[b * HH + j];
                const float r = 1.f / (1.f + __expf(-(xr[b] + ar + br)));
                const float z = 1.f / (1.f + __expf(-(xz[b] + az + bz)));
                const float n = tanhf(xn[b] + r * (an + bnb));
                const float hn = (1.f - z) * n + z * hprev;
                g_h[p ^ 1][dir][b * HH + j] = hn;
                hout[b] = hn;
            }
        }

        __syncthreads();
        if (tid == 0) {
            __threadfence();
            asm volatile("red.global.add.u32 [%0], 1;" :: "l"(mycnt) : "memory");
        }

        if (lane == 0) {
#pragma unroll
            for (int b = 0; b < BB; ++b)
                hcat[(long)(b * SS + tt) * (2 * HH) + dir * HH + j] = hout[b];
        }
        if (step + 1 < SS) {
            const int tn_ = dir ? (SS - 2 - step) : (step + 1);
#pragma unroll
            for (int b = 0; b < BB; ++b) {
                const float* row = xw + (long)(b * SS + tn_) * (3 * HH);
                xr[b] = __ldg(row + j);
                xz[b] = __ldg(row + HH + j);
                xn[b] = __ldg(row + 2 * HH + j);
            }
        }
    }
}

// =====================================================================
extern "C" void kernel_launch(void* const* d_in, const int* in_sizes, int n_in,
                              void* d_out, int out_size)
{
    (void)in_sizes; (void)n_in; (void)out_size;
    const float* x     = (const float*)d_in[0];
    const float* W     = (const float*)d_in[1];
    const float* Wg    = (const float*)d_in[2];
    const float* Wih_f = (const float*)d_in[3];
    const float* Whh_f = (const float*)d_in[4];
    const float* bih_f = (const float*)d_in[5];
    const float* bhh_f = (const float*)d_in[6];
    const float* Wih_b = (const float*)d_in[7];
    const float* Whh_b = (const float*)d_in[8];
    const float* bih_b = (const float*)d_in[9];
    const float* bhh_b = (const float*)d_in[10];
    const float* Wp    = (const float*)d_in[11];
    const float* bp    = (const float*)d_in[12];
    float* out = (float*)d_out;

    float *Wx, *sc, *rinraw, *rin, *xwf, *xwb, *hcat;
    cudaGetSymbolAddress((void**)&Wx,     g_Wx);
    cudaGetSymbolAddress((void**)&sc,     g_sc);
    cudaGetSymbolAddress((void**)&rinraw, g_rinraw);
    cudaGetSymbolAddress((void**)&rin,    g_rin);
    cudaGetSymbolAddress((void**)&xwf,    g_xwf);
    cudaGetSymbolAddress((void**)&xwb,    g_xwb);
    cudaGetSymbolAddress((void**)&hcat,   g_hcat);

    const int M = BB * SS;
    const int SMEM = 98304;   // 3 stages x 32KB

    cudaFuncSetAttribute(pip_gemm<0, 1, 0>, cudaFuncAttributeMaxDynamicSharedMemorySize, SMEM);
    cudaFuncSetAttribute(pip_gemm<1, 0, 0>, cudaFuncAttributeMaxDynamicSharedMemorySize, SMEM);
    cudaFuncSetAttribute(pip_gemm<0, 0, 1>, cudaFuncAttributeMaxDynamicSharedMemorySize, SMEM);
    cudaFuncSetAttribute(pip_gemm<0, 0, 2>, cudaFuncAttributeMaxDynamicSharedMemorySize, SMEM);
    cudaFuncSetAttribute(pip_gemm<0, 0, 3>, cudaFuncAttributeMaxDynamicSharedMemorySize, SMEM);

    init_kernel<<<64, 256>>>();

    copy_x_kernel<<<(M * DD / 4) / 256, 256>>>(x, rinraw);

    // Wx = x @ W^T (split-tf32: feeds softmax logits)
    pip_gemm<0, 1, 0><<<dim3(DD / 128, M / 128, 1), 256, SMEM>>>(
        x, W, Wx, M, DD, DD, DD, DD, DD, 0, 0, 0, nullptr, nullptr, 0);

    // s[b] = Wx[b] @ x[b]^T (split-tf32 logits)
    pip_gemm<0, 1, 0><<<dim3(SS / 128, SS / 128, BB), 256, SMEM>>>(
        Wx, x, sc, SS, SS, DD, DD, DD, SS,
        (long)SS * DD, (long)SS * DD, (long)SS * SS, nullptr, nullptr, 0);

    softmax_kernel<<<M, 256>>>(sc);

    // rin_raw[:, 512:] = a[b] @ x[b]   (tf32, BMODE1)
    pip_gemm<1, 0, 0><<<dim3(DD / 128, SS / 128, BB), 256, SMEM>>>(
        sc, x, rinraw + DD, SS, DD, SS, SS, DD, 2 * DD,
        (long)SS * SS, (long)SS * DD, (long)SS * 2 * DD, nullptr, nullptr, 0);

    // rin = rin_raw * sigmoid(rin_raw @ Wg^T)
    pip_gemm<0, 0, 2><<<dim3(2 * DD / 128, M / 128, 1), 256, SMEM>>>(
        rinraw, Wg, rin, M, 2 * DD, 2 * DD, 2 * DD, 2 * DD, 2 * DD,
        0, 0, 0, nullptr, nullptr, 0);

    // xw = rin @ Wih^T + bih (both directions)
    pip_gemm<0, 0, 1><<<dim3(3 * HH / 128, M / 128, 1), 256, SMEM>>>(
        rin, Wih_f, xwf, M, 3 * HH, 2 * DD, 2 * DD, 2 * DD, 3 * HH,
        0, 0, 0, bih_f, nullptr, 0);
    pip_gemm<0, 0, 1><<<dim3(3 * HH / 128, M / 128, 1), 256, SMEM>>>(
        rin, Wih_b, xwb, M, 3 * HH, 2 * DD, 2 * DD, 2 * DD, 3 * HH,
        0, 0, 0, bih_b, nullptr, 0);

    // bidirectional GRU -> hcat [M, 1024]
    gru_kernel<<<128, 256>>>(xwf, xwb, Whh_f, Whh_b, bhh_f, bhh_b, hcat);

    // out = x + hcat @ Wp^T + bp
    pip_gemm<0, 0, 3><<<dim3(DD / 128, M / 128, 1), 256, SMEM>>>(
        hcat, Wp, out, M, DD, 2 * HH, 2 * HH, 2 * HH, DD,
        0, 0, 0, bp, x, DD);
}